// round 1
// baseline (speedup 1.0000x reference)
#include <cuda_runtime.h>
#include <cstdint>

// Problem constants
#define L    2048
#define D    1024
#define H    16
#define DH   64
#define N3D  3072
#define SCALE 0.125f  // 1/sqrt(64)

// Scratch (device globals — no allocation allowed)
__device__ float g_qkv[L * N3D];   // [L, 3D] row-major: q | k' | v
__device__ float g_ctx[L * D];     // attention output, [L, D]

// ---------------------------------------------------------------------------
// SGEMM: C[M,N] = A[M,K] @ B[K,N] + bias[N]   (+ optional rel_emb fold into
// the K-section columns [1024,2048): C[r][c] += rel_emb[(r-1)*64 + (c&63)]
// for r>=1). BM=BN=128, BK=8, 256 threads, 8x8 microtile.
// ---------------------------------------------------------------------------
__global__ __launch_bounds__(256) void sgemm_bias_kernel(
    const float* __restrict__ A, const float* __restrict__ B,
    const float* __restrict__ bias, float* __restrict__ C,
    int M, int N, int K, const float* __restrict__ rel)
{
    __shared__ float As[8][128];
    __shared__ float Bs[8][128];

    const int bm = blockIdx.y * 128;
    const int bn = blockIdx.x * 128;
    const int tid = threadIdx.x;
    const int tx = tid & 15;   // 0..15
    const int ty = tid >> 4;   // 0..15

    float acc[8][8];
#pragma unroll
    for (int i = 0; i < 8; i++)
#pragma unroll
        for (int j = 0; j < 8; j++) acc[i][j] = 0.f;

    // A-load indices: 256 threads cover 128 rows x 2 float4
    const int ar  = tid >> 1;        // 0..127
    const int ac4 = (tid & 1) * 4;   // 0 or 4
    // B-load indices: 8 rows x 32 float4
    const int br  = tid >> 5;        // 0..7
    const int bc4 = (tid & 31) * 4;  // 0..124

    for (int k0 = 0; k0 < K; k0 += 8) {
        float4 av = *(const float4*)(A + (size_t)(bm + ar) * K + k0 + ac4);
        As[ac4 + 0][ar] = av.x;
        As[ac4 + 1][ar] = av.y;
        As[ac4 + 2][ar] = av.z;
        As[ac4 + 3][ar] = av.w;

        float4 bv = *(const float4*)(B + (size_t)(k0 + br) * N + bn + bc4);
        *(float4*)&Bs[br][bc4] = bv;

        __syncthreads();

#pragma unroll
        for (int kk = 0; kk < 8; kk++) {
            float4 a0 = *(const float4*)&As[kk][ty * 8];
            float4 a1 = *(const float4*)&As[kk][ty * 8 + 4];
            float4 b0 = *(const float4*)&Bs[kk][tx * 8];
            float4 b1 = *(const float4*)&Bs[kk][tx * 8 + 4];
            float a[8] = {a0.x, a0.y, a0.z, a0.w, a1.x, a1.y, a1.z, a1.w};
            float b[8] = {b0.x, b0.y, b0.z, b0.w, b1.x, b1.y, b1.z, b1.w};
#pragma unroll
            for (int i = 0; i < 8; i++)
#pragma unroll
                for (int j = 0; j < 8; j++) acc[i][j] = fmaf(a[i], b[j], acc[i][j]);
        }
        __syncthreads();
    }

    // Epilogue: bias (+ rel fold)
#pragma unroll
    for (int i = 0; i < 8; i++) {
        const int row = bm + ty * 8 + i;
        float* crow = C + (size_t)row * N;
#pragma unroll
        for (int j = 0; j < 8; j++) {
            const int col = bn + tx * 8 + j;
            float v = acc[i][j] + bias[col];
            if (rel != nullptr && row >= 1 && col >= 1024 && col < 2048) {
                v += rel[(size_t)(row - 1) * 64 + (col & 63)];
            }
            crow[col] = v;
        }
    }
}

// ---------------------------------------------------------------------------
// Flash attention, fp32, non-causal. 1 thread = 1 query row.
// Block: 128 threads (128 query rows). KV tiles of 64 keys in smem.
// grid = (L/128, H)
// ---------------------------------------------------------------------------
__global__ __launch_bounds__(128) void flash_kernel()
{
    const int h   = blockIdx.y;
    const int tid = threadIdx.x;
    const int row = blockIdx.x * 128 + tid;

    __shared__ float4 Ks[64][16];
    __shared__ float4 Vs[64][16];

    float q[64], o[64];
    {
        const float* qp = g_qkv + (size_t)row * N3D + h * DH;
#pragma unroll
        for (int c = 0; c < 16; c++) {
            float4 qv = *(const float4*)(qp + c * 4);
            q[4 * c + 0] = qv.x * SCALE;
            q[4 * c + 1] = qv.y * SCALE;
            q[4 * c + 2] = qv.z * SCALE;
            q[4 * c + 3] = qv.w * SCALE;
        }
    }
#pragma unroll
    for (int d = 0; d < 64; d++) o[d] = 0.f;
    float m = -1e30f, l = 0.f;

    for (int j0 = 0; j0 < L; j0 += 64) {
        // cooperative load: K' and V tiles (64 rows x 64 dims, as float4)
        const float* kbase = g_qkv + (size_t)j0 * N3D + 1024 + h * DH;
        const float* vbase = kbase + 1024;
        for (int t = tid; t < 64 * 16; t += 128) {
            const int r = t >> 4, c = t & 15;
            Ks[r][c] = *(const float4*)(kbase + (size_t)r * N3D + c * 4);
            Vs[r][c] = *(const float4*)(vbase + (size_t)r * N3D + c * 4);
        }
        __syncthreads();

#pragma unroll 1
        for (int jj = 0; jj < 64; jj += 16) {
            float s[16];
            float mt = m;
#pragma unroll
            for (int j = 0; j < 16; j++) {
                float acc = 0.f;
#pragma unroll
                for (int c = 0; c < 16; c++) {
                    float4 kk = Ks[jj + j][c];
                    acc = fmaf(q[4 * c + 0], kk.x, acc);
                    acc = fmaf(q[4 * c + 1], kk.y, acc);
                    acc = fmaf(q[4 * c + 2], kk.z, acc);
                    acc = fmaf(q[4 * c + 3], kk.w, acc);
                }
                s[j] = acc;
                mt = fmaxf(mt, acc);
            }
            const float rescale = __expf(m - mt);
            m = mt;
            l *= rescale;
#pragma unroll
            for (int d = 0; d < 64; d++) o[d] *= rescale;
#pragma unroll
            for (int j = 0; j < 16; j++) {
                const float p = __expf(s[j] - m);
                l += p;
#pragma unroll
                for (int c = 0; c < 16; c++) {
                    float4 vv = Vs[jj + j][c];
                    o[4 * c + 0] = fmaf(p, vv.x, o[4 * c + 0]);
                    o[4 * c + 1] = fmaf(p, vv.y, o[4 * c + 1]);
                    o[4 * c + 2] = fmaf(p, vv.z, o[4 * c + 2]);
                    o[4 * c + 3] = fmaf(p, vv.w, o[4 * c + 3]);
                }
            }
        }
        __syncthreads();
    }

    const float inv = 1.f / l;
    float* op = g_ctx + (size_t)row * D + h * DH;
#pragma unroll
    for (int c = 0; c < 16; c++) {
        float4 ov;
        ov.x = o[4 * c + 0] * inv;
        ov.y = o[4 * c + 1] * inv;
        ov.z = o[4 * c + 2] * inv;
        ov.w = o[4 * c + 3] * inv;
        *(float4*)(op + c * 4) = ov;
    }
}

// ---------------------------------------------------------------------------
// Launch
// ---------------------------------------------------------------------------
extern "C" void kernel_launch(void* const* d_in, const int* in_sizes, int n_in,
                              void* d_out, int out_size)
{
    const float* x    = (const float*)d_in[0];  // [1,2048,1024]
    const float* Wqkv = (const float*)d_in[1];  // [1024,3072]
    const float* bqkv = (const float*)d_in[2];  // [3072]
    const float* Wout = (const float*)d_in[3];  // [1024,1024]
    const float* bout = (const float*)d_in[4];  // [1024]
    const float* rel  = (const float*)d_in[5];  // [4095,64]
    float* out = (float*)d_out;                 // [1,2048,1024]

    void* qkv_ptr = nullptr;
    void* ctx_ptr = nullptr;
    cudaGetSymbolAddress(&qkv_ptr, g_qkv);
    cudaGetSymbolAddress(&ctx_ptr, g_ctx);
    float* qkv = (float*)qkv_ptr;
    float* ctx = (float*)ctx_ptr;

    // 1) qkv = x @ Wqkv + bqkv, with rel_emb shift folded into K columns
    {
        dim3 grid(N3D / 128, L / 128);
        sgemm_bias_kernel<<<grid, 256>>>(x, Wqkv, bqkv, qkv, L, N3D, D, rel);
    }

    // 2) flash attention per head
    {
        dim3 grid(L / 128, H);
        flash_kernel<<<grid, 128>>>();
    }

    // 3) out = ctx @ Wout + bout
    {
        dim3 grid(D / 128, L / 128);
        sgemm_bias_kernel<<<grid, 256>>>(ctx, Wout, bout, out, L, D, D, nullptr);
    }
}

// round 3
// speedup vs baseline: 3.8496x; 3.8496x over previous
#include <cuda_runtime.h>
#include <cuda_fp16.h>
#include <cstdint>

#define L    2048
#define D    1024
#define H    16
#define DH   64
#define N3D  3072
#define SCALE 0.125f

__device__ float g_qkv[L * N3D];   // q | k' (rel folded) | v
__device__ float g_ctx[L * D];

// ---------------------------------------------------------------------------
// helpers
// ---------------------------------------------------------------------------
__device__ __forceinline__ uint32_t pack_h2(__half a, __half b) {
    __half2 h = __halves2half2(a, b);
    return *(uint32_t*)&h;
}
// split (x,y) into fp16 hi/lo pairs packed as half2
__device__ __forceinline__ void split2(float x, float y, uint32_t& hi, uint32_t& lo) {
    __half hx = __float2half_rn(x), hy = __float2half_rn(y);
    __half lx = __float2half_rn(x - __half2float(hx));
    __half ly = __float2half_rn(y - __half2float(hy));
    hi = pack_h2(hx, hy);
    lo = pack_h2(lx, ly);
}
__device__ __forceinline__ void cvt_store4(float4 f, __half* hp, __half* lp) {
    uint32_t h0, l0, h1, l1;
    split2(f.x, f.y, h0, l0);
    split2(f.z, f.w, h1, l1);
    *(uint2*)hp = make_uint2(h0, h1);
    *(uint2*)lp = make_uint2(l0, l1);
}
__device__ __forceinline__ void mma_f16(float* d, const uint32_t* a, uint32_t b0, uint32_t b1) {
    asm volatile(
        "mma.sync.aligned.m16n8k16.row.col.f32.f16.f16.f32 "
        "{%0,%1,%2,%3},{%4,%5,%6,%7},{%8,%9},{%0,%1,%2,%3};\n"
        : "+f"(d[0]), "+f"(d[1]), "+f"(d[2]), "+f"(d[3])
        : "r"(a[0]), "r"(a[1]), "r"(a[2]), "r"(a[3]), "r"(b0), "r"(b1));
}
__device__ __forceinline__ void ldsm_x4(uint32_t* r, uint32_t addr) {
    asm volatile("ldmatrix.sync.aligned.m8n8.x4.shared.b16 {%0,%1,%2,%3},[%4];\n"
                 : "=r"(r[0]), "=r"(r[1]), "=r"(r[2]), "=r"(r[3]) : "r"(addr));
}
__device__ __forceinline__ void ldsm_x4_t(uint32_t* r, uint32_t addr) {
    asm volatile("ldmatrix.sync.aligned.m8n8.x4.trans.shared.b16 {%0,%1,%2,%3},[%4];\n"
                 : "=r"(r[0]), "=r"(r[1]), "=r"(r[2]), "=r"(r[3]) : "r"(addr));
}
__device__ __forceinline__ uint32_t saddr(const void* p) {
    return (uint32_t)__cvta_generic_to_shared(p);
}

// ---------------------------------------------------------------------------
// split-fp16 GEMM: C = A[M,K] @ B[K,N] + bias (+ rel fold, cols [1024,2048))
// 256 thr, tile 128x128, BK=32, warps 4(m)x2(n), 3-term Markidis mma.
// ---------------------------------------------------------------------------
#define SA 40    // As row stride in halves
#define SB 136   // Bs row stride in halves

__global__ __launch_bounds__(256, 1) void gemm_f16s(
    const float* __restrict__ A, const float* __restrict__ B,
    const float* __restrict__ bias, float* __restrict__ C,
    int M, int N, int K, const float* __restrict__ rel)
{
    __shared__ __align__(16) __half Ash[128 * SA], Asl[128 * SA];
    __shared__ __align__(16) __half Bsh[32 * SB],  Bsl[32 * SB];

    const int tid = threadIdx.x;
    const int warp = tid >> 5, lane = tid & 31;
    const int gid = lane >> 2, tg = lane & 3;
    const int bm = blockIdx.y * 128, bn = blockIdx.x * 128;
    const int wm = (warp >> 1) * 32, wn = (warp & 1) * 64;

    float acc[2][8][4];
#pragma unroll
    for (int mt = 0; mt < 2; mt++)
#pragma unroll
        for (int nt = 0; nt < 8; nt++)
#pragma unroll
            for (int i = 0; i < 4; i++) acc[mt][nt][i] = 0.f;

    // ldmatrix lane offsets
    const int l15 = lane & 15, lhi = lane >> 4;                 // A mats
    const int krow = ((lane >> 3) & 1) * 8 + (lane & 7);        // B mats
    const uint32_t offA = (uint32_t)(((wm + l15) * SA + lhi * 8) * 2);
    const uint32_t ah_base = saddr(Ash) + offA;
    const uint32_t al_base = saddr(Asl) + offA;
    const uint32_t offB = (uint32_t)((krow * SB + wn + lhi * 8) * 2);
    const uint32_t bh_base = saddr(Bsh) + offB;
    const uint32_t bl_base = saddr(Bsl) + offB;

    float4 ra[4], rb[4];
    const int nkt = K / 32;

    // prologue
#pragma unroll
    for (int i = 0; i < 4; i++) {
        int idx = tid + i * 256;
        ra[i] = *(const float4*)(A + (size_t)(bm + (idx >> 3)) * K + (idx & 7) * 4);
        rb[i] = *(const float4*)(B + (size_t)(idx >> 5) * N + bn + (idx & 31) * 4);
    }
#pragma unroll
    for (int i = 0; i < 4; i++) {
        int idx = tid + i * 256;
        int am = idx >> 3, ak = (idx & 7) * 4;
        cvt_store4(ra[i], &Ash[am * SA + ak], &Asl[am * SA + ak]);
        int bk = idx >> 5, bnn = (idx & 31) * 4;
        cvt_store4(rb[i], &Bsh[bk * SB + bnn], &Bsl[bk * SB + bnn]);
    }
    __syncthreads();

    for (int kt = 0; kt < nkt; kt++) {
        const bool nxt = (kt + 1) < nkt;
        if (nxt) {
            const int k0 = (kt + 1) * 32;
#pragma unroll
            for (int i = 0; i < 4; i++) {
                int idx = tid + i * 256;
                ra[i] = *(const float4*)(A + (size_t)(bm + (idx >> 3)) * K + k0 + (idx & 7) * 4);
                rb[i] = *(const float4*)(B + (size_t)(k0 + (idx >> 5)) * N + bn + (idx & 31) * 4);
            }
        }

#pragma unroll
        for (int ks = 0; ks < 2; ks++) {
            uint32_t Ah[2][4], Al[2][4];
#pragma unroll
            for (int mt = 0; mt < 2; mt++) {
                const uint32_t ao = (uint32_t)(mt * 16 * SA * 2 + ks * 32);
                ldsm_x4(Ah[mt], ah_base + ao);
                ldsm_x4(Al[mt], al_base + ao);
            }
#pragma unroll
            for (int p = 0; p < 4; p++) {
                uint32_t Bh[4], Bl[4];
                const uint32_t bo = (uint32_t)(ks * 16 * SB * 2 + p * 32);
                ldsm_x4_t(Bh, bh_base + bo);
                ldsm_x4_t(Bl, bl_base + bo);
#pragma unroll
                for (int mt = 0; mt < 2; mt++) {
                    mma_f16(acc[mt][2 * p],     Ah[mt], Bh[0], Bh[1]);
                    mma_f16(acc[mt][2 * p],     Ah[mt], Bl[0], Bl[1]);
                    mma_f16(acc[mt][2 * p],     Al[mt], Bh[0], Bh[1]);
                    mma_f16(acc[mt][2 * p + 1], Ah[mt], Bh[2], Bh[3]);
                    mma_f16(acc[mt][2 * p + 1], Ah[mt], Bl[2], Bl[3]);
                    mma_f16(acc[mt][2 * p + 1], Al[mt], Bh[2], Bh[3]);
                }
            }
        }
        __syncthreads();
        if (nxt) {
#pragma unroll
            for (int i = 0; i < 4; i++) {
                int idx = tid + i * 256;
                int am = idx >> 3, ak = (idx & 7) * 4;
                cvt_store4(ra[i], &Ash[am * SA + ak], &Asl[am * SA + ak]);
                int bk = idx >> 5, bnn = (idx & 31) * 4;
                cvt_store4(rb[i], &Bsh[bk * SB + bnn], &Bsl[bk * SB + bnn]);
            }
            __syncthreads();
        }
    }

    // epilogue
#pragma unroll
    for (int mt = 0; mt < 2; mt++) {
#pragma unroll
        for (int nt = 0; nt < 8; nt++) {
            const int col = bn + wn + nt * 8 + 2 * tg;
            const float bi0 = bias[col], bi1 = bias[col + 1];
#pragma unroll
            for (int hf = 0; hf < 2; hf++) {
                const int row = bm + wm + mt * 16 + gid + hf * 8;
                float v0 = acc[mt][nt][hf * 2 + 0] + bi0;
                float v1 = acc[mt][nt][hf * 2 + 1] + bi1;
                if (rel != nullptr && row >= 1 && col >= 1024 && col < 2048) {
                    v0 += rel[(size_t)(row - 1) * 64 + (col & 63)];
                    v1 += rel[(size_t)(row - 1) * 64 + ((col + 1) & 63)];
                }
                *(float2*)(C + (size_t)row * N + col) = make_float2(v0, v1);
            }
        }
    }
}

// ---------------------------------------------------------------------------
// Flash attention, split-fp16 mma. 128 thr / 4 warps / 64 q-rows per block,
// 64-key KV tiles. grid = (L/64, H)
// ---------------------------------------------------------------------------
#define SK 72    // K/V smem row stride in halves

__global__ __launch_bounds__(128, 2) void flash_f16s()
{
    __shared__ __align__(16) __half Ksh[64 * SK], Ksl[64 * SK];
    __shared__ __align__(16) __half Vsh[64 * SK], Vsl[64 * SK];

    const int h = blockIdx.y;
    const int tid = threadIdx.x;
    const int warp = tid >> 5, lane = tid & 31;
    const int gid = lane >> 2, tg = lane & 3;
    const int qrow0 = blockIdx.x * 64 + warp * 16;

    // V ldmatrix lane offsets
    const int krow = ((lane >> 3) & 1) * 8 + (lane & 7);
    const int ncol = (lane >> 4) * 8;
    const uint32_t offV = (uint32_t)((krow * SK + ncol) * 2);
    const uint32_t vh_base = saddr(Vsh) + offV;
    const uint32_t vl_base = saddr(Vsl) + offV;

    // Q fragments (hi/lo), pre-scaled
    uint32_t qh[4][4], ql[4][4];
    {
        const float* qp = g_qkv + (size_t)qrow0 * N3D + h * DH;
#pragma unroll
        for (int ks = 0; ks < 4; ks++) {
            const int c = ks * 16 + 2 * tg;
            float2 v0 = *(const float2*)(qp + (size_t)gid * N3D + c);
            float2 v1 = *(const float2*)(qp + (size_t)(gid + 8) * N3D + c);
            float2 v2 = *(const float2*)(qp + (size_t)gid * N3D + c + 8);
            float2 v3 = *(const float2*)(qp + (size_t)(gid + 8) * N3D + c + 8);
            split2(v0.x * SCALE, v0.y * SCALE, qh[ks][0], ql[ks][0]);
            split2(v1.x * SCALE, v1.y * SCALE, qh[ks][1], ql[ks][1]);
            split2(v2.x * SCALE, v2.y * SCALE, qh[ks][2], ql[ks][2]);
            split2(v3.x * SCALE, v3.y * SCALE, qh[ks][3], ql[ks][3]);
        }
    }

    float o[8][4];
#pragma unroll
    for (int nt = 0; nt < 8; nt++)
#pragma unroll
        for (int i = 0; i < 4; i++) o[nt][i] = 0.f;
    float m0 = -1e30f, m1 = -1e30f, l0 = 0.f, l1 = 0.f;

    for (int j0 = 0; j0 < L; j0 += 64) {
        const float* kb = g_qkv + (size_t)j0 * N3D + D + h * DH;
        const float* vb = kb + D;
#pragma unroll
        for (int i = 0; i < 8; i++) {
            int idx = tid + i * 128;
            int r = idx >> 4, c4 = (idx & 15) * 4;
            float4 kv = *(const float4*)(kb + (size_t)r * N3D + c4);
            float4 vv = *(const float4*)(vb + (size_t)r * N3D + c4);
            cvt_store4(kv, &Ksh[r * SK + c4], &Ksl[r * SK + c4]);
            cvt_store4(vv, &Vsh[r * SK + c4], &Vsl[r * SK + c4]);
        }
        __syncthreads();

        // S = Q @ K'^T
        float s[8][4];
#pragma unroll
        for (int nt = 0; nt < 8; nt++)
#pragma unroll
            for (int i = 0; i < 4; i++) s[nt][i] = 0.f;
#pragma unroll
        for (int ks = 0; ks < 4; ks++) {
            const int kc = ks * 16 + 2 * tg;
#pragma unroll
            for (int nt = 0; nt < 8; nt++) {
                const int rr = (nt * 8 + gid) * SK;
                uint32_t kh0 = *(const uint32_t*)(Ksh + rr + kc);
                uint32_t kh1 = *(const uint32_t*)(Ksh + rr + kc + 8);
                uint32_t kl0 = *(const uint32_t*)(Ksl + rr + kc);
                uint32_t kl1 = *(const uint32_t*)(Ksl + rr + kc + 8);
                mma_f16(s[nt], qh[ks], kh0, kh1);
                mma_f16(s[nt], qh[ks], kl0, kl1);
                mma_f16(s[nt], ql[ks], kh0, kh1);
            }
        }

        // online softmax (rows gid / gid+8)
        float tm0 = -1e30f, tm1 = -1e30f;
#pragma unroll
        for (int nt = 0; nt < 8; nt++) {
            tm0 = fmaxf(tm0, fmaxf(s[nt][0], s[nt][1]));
            tm1 = fmaxf(tm1, fmaxf(s[nt][2], s[nt][3]));
        }
        tm0 = fmaxf(tm0, __shfl_xor_sync(0xffffffffu, tm0, 1));
        tm0 = fmaxf(tm0, __shfl_xor_sync(0xffffffffu, tm0, 2));
        tm1 = fmaxf(tm1, __shfl_xor_sync(0xffffffffu, tm1, 1));
        tm1 = fmaxf(tm1, __shfl_xor_sync(0xffffffffu, tm1, 2));
        const float nm0 = fmaxf(m0, tm0), nm1 = fmaxf(m1, tm1);
        const float r0 = __expf(m0 - nm0), r1 = __expf(m1 - nm1);
        m0 = nm0; m1 = nm1;
        l0 *= r0; l1 *= r1;
#pragma unroll
        for (int nt = 0; nt < 8; nt++) {
            o[nt][0] *= r0; o[nt][1] *= r0;
            o[nt][2] *= r1; o[nt][3] *= r1;
            s[nt][0] = __expf(s[nt][0] - m0);
            s[nt][1] = __expf(s[nt][1] - m0);
            s[nt][2] = __expf(s[nt][2] - m1);
            s[nt][3] = __expf(s[nt][3] - m1);
            l0 += s[nt][0] + s[nt][1];
            l1 += s[nt][2] + s[nt][3];
        }

        // P @ V : accumulator col-pairs ARE the fp16 A-fragment k-pairs
#pragma unroll
        for (int ks = 0; ks < 4; ks++) {
            uint32_t ah[4], al[4];
            split2(s[2 * ks][0],     s[2 * ks][1],     ah[0], al[0]);
            split2(s[2 * ks][2],     s[2 * ks][3],     ah[1], al[1]);
            split2(s[2 * ks + 1][0], s[2 * ks + 1][1], ah[2], al[2]);
            split2(s[2 * ks + 1][2], s[2 * ks + 1][3], ah[3], al[3]);
#pragma unroll
            for (int p = 0; p < 4; p++) {
                uint32_t Vh[4], Vl[4];
                const uint32_t vo = (uint32_t)(ks * 16 * SK * 2 + p * 32);
                ldsm_x4_t(Vh, vh_base + vo);
                ldsm_x4_t(Vl, vl_base + vo);
                mma_f16(o[2 * p],     ah, Vh[0], Vh[1]);
                mma_f16(o[2 * p],     ah, Vl[0], Vl[1]);
                mma_f16(o[2 * p],     al, Vh[0], Vh[1]);
                mma_f16(o[2 * p + 1], ah, Vh[2], Vh[3]);
                mma_f16(o[2 * p + 1], ah, Vl[2], Vl[3]);
                mma_f16(o[2 * p + 1], al, Vh[2], Vh[3]);
            }
        }
        __syncthreads();
    }

    l0 += __shfl_xor_sync(0xffffffffu, l0, 1);
    l0 += __shfl_xor_sync(0xffffffffu, l0, 2);
    l1 += __shfl_xor_sync(0xffffffffu, l1, 1);
    l1 += __shfl_xor_sync(0xffffffffu, l1, 2);
    const float inv0 = 1.f / l0, inv1 = 1.f / l1;

    float* op = g_ctx + (size_t)qrow0 * D + h * DH;
#pragma unroll
    for (int nt = 0; nt < 8; nt++) {
        const int col = nt * 8 + 2 * tg;
        *(float2*)(op + (size_t)gid * D + col) =
            make_float2(o[nt][0] * inv0, o[nt][1] * inv0);
        *(float2*)(op + (size_t)(gid + 8) * D + col) =
            make_float2(o[nt][2] * inv1, o[nt][3] * inv1);
    }
}

// ---------------------------------------------------------------------------
extern "C" void kernel_launch(void* const* d_in, const int* in_sizes, int n_in,
                              void* d_out, int out_size)
{
    const float* x    = (const float*)d_in[0];
    const float* Wqkv = (const float*)d_in[1];
    const float* bqkv = (const float*)d_in[2];
    const float* Wout = (const float*)d_in[3];
    const float* bout = (const float*)d_in[4];
    const float* rel  = (const float*)d_in[5];
    float* out = (float*)d_out;

    void* qkv_ptr = nullptr;
    void* ctx_ptr = nullptr;
    cudaGetSymbolAddress(&qkv_ptr, g_qkv);
    cudaGetSymbolAddress(&ctx_ptr, g_ctx);
    float* qkv = (float*)qkv_ptr;
    float* ctx = (float*)ctx_ptr;

    {
        dim3 grid(N3D / 128, L / 128);
        gemm_f16s<<<grid, 256>>>(x, Wqkv, bqkv, qkv, L, N3D, D, rel);
    }
    {
        dim3 grid(L / 64, H);
        flash_f16s<<<grid, 128>>>();
    }
    {
        dim3 grid(D / 128, L / 128);
        gemm_f16s<<<grid, 256>>>(ctx, Wout, bout, out, L, D, D, nullptr);
    }
}

// round 4
// speedup vs baseline: 3.9056x; 1.0145x over previous
#include <cuda_runtime.h>
#include <cuda_fp16.h>
#include <cstdint>

#define L    2048
#define D    1024
#define H    16
#define DH   64
#define N3D  3072
#define SCALE 0.125f

// Scratch (device globals — no allocation allowed)
__device__ __half g_xh[L * D],     g_xl[L * D];
__device__ __half g_wqh[D * N3D],  g_wql[D * N3D];
__device__ __half g_woh[D * D],    g_wol[D * D];
__device__ __half g_qkvh[L * N3D], g_qkvl[L * N3D];   // q | k'(rel+scale folded) | v
__device__ __half g_ctxh[L * D],   g_ctxl[L * D];

// ---------------------------------------------------------------------------
// helpers
// ---------------------------------------------------------------------------
__device__ __forceinline__ uint32_t cvt2(float x, float y) {
    __half2 h = __float22half2_rn(make_float2(x, y));
    return *(uint32_t*)&h;
}
__device__ __forceinline__ void split2(float x, float y, uint32_t& hi, uint32_t& lo) {
    __half2 h = __float22half2_rn(make_float2(x, y));
    float2 hf = __half22float2(h);
    hi = *(uint32_t*)&h;
    lo = cvt2(x - hf.x, y - hf.y);
}
__device__ __forceinline__ void mma_f16(float* d, const uint32_t* a, uint32_t b0, uint32_t b1) {
    asm volatile(
        "mma.sync.aligned.m16n8k16.row.col.f32.f16.f16.f32 "
        "{%0,%1,%2,%3},{%4,%5,%6,%7},{%8,%9},{%0,%1,%2,%3};\n"
        : "+f"(d[0]), "+f"(d[1]), "+f"(d[2]), "+f"(d[3])
        : "r"(a[0]), "r"(a[1]), "r"(a[2]), "r"(a[3]), "r"(b0), "r"(b1));
}
__device__ __forceinline__ void ldsm_x4(uint32_t* r, uint32_t addr) {
    asm volatile("ldmatrix.sync.aligned.m8n8.x4.shared.b16 {%0,%1,%2,%3},[%4];\n"
                 : "=r"(r[0]), "=r"(r[1]), "=r"(r[2]), "=r"(r[3]) : "r"(addr));
}
__device__ __forceinline__ void ldsm_x4_t(uint32_t* r, uint32_t addr) {
    asm volatile("ldmatrix.sync.aligned.m8n8.x4.trans.shared.b16 {%0,%1,%2,%3},[%4];\n"
                 : "=r"(r[0]), "=r"(r[1]), "=r"(r[2]), "=r"(r[3]) : "r"(addr));
}
__device__ __forceinline__ uint32_t saddr(const void* p) {
    return (uint32_t)__cvta_generic_to_shared(p);
}
__device__ __forceinline__ void cp16(uint32_t s, const void* g) {
    asm volatile("cp.async.cg.shared.global [%0],[%1],16;\n" :: "r"(s), "l"(g));
}
__device__ __forceinline__ void cp_commit() { asm volatile("cp.async.commit_group;\n"); }
template <int N> __device__ __forceinline__ void cp_wait() {
    asm volatile("cp.async.wait_group %0;\n" :: "n"(N));
}

// ---------------------------------------------------------------------------
// one-pass fp32 -> (hi,lo) split
// ---------------------------------------------------------------------------
__global__ __launch_bounds__(256) void split_kernel(
    const float* __restrict__ src, __half* __restrict__ hi, __half* __restrict__ lo, int n4)
{
    int i = blockIdx.x * 256 + threadIdx.x;
    if (i < n4) {
        float4 f = ((const float4*)src)[i];
        uint32_t h0, l0, h1, l1;
        split2(f.x, f.y, h0, l0);
        split2(f.z, f.w, h1, l1);
        ((uint2*)hi)[i] = make_uint2(h0, h1);
        ((uint2*)lo)[i] = make_uint2(l0, l1);
    }
}

// ---------------------------------------------------------------------------
// split-fp16 GEMM, pre-split operands, cp.async 2-stage, BK=16.
// 256 thr, tile 128x128, warps 4(m)x2(n).
// If Ch != null: write split halves (with rel fold + 0.125 scale on cols
// [1024,2048)). Else: write fp32 to Cf.
// ---------------------------------------------------------------------------
#define SA 24
#define SB 136

__global__ __launch_bounds__(256, 2) void gemm_f16p(
    const __half* __restrict__ Ah, const __half* __restrict__ Al,
    const __half* __restrict__ Bh, const __half* __restrict__ Bl,
    const float* __restrict__ bias,
    float* __restrict__ Cf, __half* __restrict__ Ch, __half* __restrict__ Cl,
    int M, int N, int K, const float* __restrict__ rel)
{
    __shared__ __align__(16) __half Ash[2][128 * SA], Asl[2][128 * SA];
    __shared__ __align__(16) __half Bsh[2][16 * SB],  Bsl[2][16 * SB];

    const int tid = threadIdx.x;
    const int warp = tid >> 5, lane = tid & 31;
    const int gid = lane >> 2, tg = lane & 3;
    const int bm = blockIdx.y * 128, bn = blockIdx.x * 128;
    const int wm = (warp >> 1) * 32, wn = (warp & 1) * 64;

    float acc[2][8][4];
#pragma unroll
    for (int mt = 0; mt < 2; mt++)
#pragma unroll
        for (int nt = 0; nt < 8; nt++)
#pragma unroll
            for (int i = 0; i < 4; i++) acc[mt][nt][i] = 0.f;

    // cp.async indices: A: 128 rows x 2 chunks; B: 16 rows x 16 chunks
    const int arow = tid >> 1, ac = (tid & 1) * 8;
    const int brow = tid >> 4, bc = (tid & 15) * 8;
    const size_t agoff = (size_t)(bm + arow) * K + ac;
    const size_t bgoff = (size_t)brow * N + bn + bc;
    const uint32_t asoff = (uint32_t)((arow * SA + ac) * 2);
    const uint32_t bsoff = (uint32_t)((brow * SB + bc) * 2);

    // ldmatrix offsets
    const int l15 = lane & 15, lhi = lane >> 4;
    const int krow = ((lane >> 3) & 1) * 8 + (lane & 7);
    const uint32_t offA = (uint32_t)(((wm + l15) * SA + lhi * 8) * 2);
    const uint32_t offB = (uint32_t)((krow * SB + wn + lhi * 8) * 2);

    const int nkt = K >> 4;

    // prologue: stage 0
    cp16(saddr(Ash[0]) + asoff, Ah + agoff);
    cp16(saddr(Asl[0]) + asoff, Al + agoff);
    cp16(saddr(Bsh[0]) + bsoff, Bh + bgoff);
    cp16(saddr(Bsl[0]) + bsoff, Bl + bgoff);
    cp_commit();

    for (int kt = 0; kt < nkt; kt++) {
        const int b = kt & 1;
        if (kt + 1 < nkt) {
            const int nb = (kt + 1) & 1;
            const size_t ka = agoff + (kt + 1) * 16;
            const size_t kb = bgoff + (size_t)(kt + 1) * 16 * N;
            cp16(saddr(Ash[nb]) + asoff, Ah + ka);
            cp16(saddr(Asl[nb]) + asoff, Al + ka);
            cp16(saddr(Bsh[nb]) + bsoff, Bh + kb);
            cp16(saddr(Bsl[nb]) + bsoff, Bl + kb);
            cp_commit();
            cp_wait<1>();
        } else {
            cp_wait<0>();
        }
        __syncthreads();

        uint32_t Afh[2][4], Afl[2][4];
        const uint32_t ah_base = saddr(Ash[b]) + offA;
        const uint32_t al_base = saddr(Asl[b]) + offA;
#pragma unroll
        for (int mt = 0; mt < 2; mt++) {
            ldsm_x4(Afh[mt], ah_base + mt * 16 * SA * 2);
            ldsm_x4(Afl[mt], al_base + mt * 16 * SA * 2);
        }
        const uint32_t bh_base = saddr(Bsh[b]) + offB;
        const uint32_t bl_base = saddr(Bsl[b]) + offB;
#pragma unroll
        for (int p = 0; p < 4; p++) {
            uint32_t Bfh[4], Bfl[4];
            ldsm_x4_t(Bfh, bh_base + p * 32);
            ldsm_x4_t(Bfl, bl_base + p * 32);
#pragma unroll
            for (int mt = 0; mt < 2; mt++) {
                mma_f16(acc[mt][2 * p],     Afh[mt], Bfh[0], Bfh[1]);
                mma_f16(acc[mt][2 * p],     Afh[mt], Bfl[0], Bfl[1]);
                mma_f16(acc[mt][2 * p],     Afl[mt], Bfh[0], Bfh[1]);
                mma_f16(acc[mt][2 * p + 1], Afh[mt], Bfh[2], Bfh[3]);
                mma_f16(acc[mt][2 * p + 1], Afh[mt], Bfl[2], Bfl[3]);
                mma_f16(acc[mt][2 * p + 1], Afl[mt], Bfh[2], Bfh[3]);
            }
        }
        __syncthreads();
    }

    // epilogue
#pragma unroll
    for (int mt = 0; mt < 2; mt++) {
#pragma unroll
        for (int nt = 0; nt < 8; nt++) {
            const int col = bn + wn + nt * 8 + 2 * tg;
            const float bi0 = bias[col], bi1 = bias[col + 1];
#pragma unroll
            for (int hf = 0; hf < 2; hf++) {
                const int row = bm + wm + mt * 16 + gid + hf * 8;
                float v0 = acc[mt][nt][hf * 2 + 0] + bi0;
                float v1 = acc[mt][nt][hf * 2 + 1] + bi1;
                if (Ch != nullptr) {
                    if (col >= 1024 && col < 2048) {       // K' section
                        if (row >= 1) {
                            v0 += rel[(size_t)(row - 1) * 64 + (col & 63)];
                            v1 += rel[(size_t)(row - 1) * 64 + ((col + 1) & 63)];
                        }
                        v0 *= SCALE; v1 *= SCALE;          // fold 1/sqrt(dh), exact pow2
                    }
                    uint32_t h, l;
                    split2(v0, v1, h, l);
                    *(uint32_t*)(Ch + (size_t)row * N + col) = h;
                    *(uint32_t*)(Cl + (size_t)row * N + col) = l;
                } else {
                    *(float2*)(Cf + (size_t)row * N + col) = make_float2(v0, v1);
                }
            }
        }
    }
}

// ---------------------------------------------------------------------------
// Flash attention: pre-split qkv halves, cp.async double-buffered 32-key
// tiles, 256 thr / 8 warps / 128 q-rows per block. grid = (L/128, H).
// S = 3-term; P@V: P single fp16 term, V split (2-term).
// ---------------------------------------------------------------------------
#define SK 72

__global__ __launch_bounds__(256, 2) void flash_f16p()
{
    __shared__ __align__(16) __half Ksh[2][32 * SK], Ksl[2][32 * SK];
    __shared__ __align__(16) __half Vsh[2][32 * SK], Vsl[2][32 * SK];

    const int h = blockIdx.y;
    const int tid = threadIdx.x;
    const int warp = tid >> 5, lane = tid & 31;
    const int gid = lane >> 2, tg = lane & 3;
    const int qrow0 = blockIdx.x * 128 + warp * 16;

    // cp.async indices: 32 rows x 8 chunks per array -> 1 chunk/thread
    const int krow_ld = tid >> 3, kc8 = (tid & 7) * 8;
    const size_t kgoff = (size_t)krow_ld * N3D + D + h * DH + kc8;       // K'
    const size_t vgoff = kgoff + D;                                      // V
    const uint32_t ksoff = (uint32_t)((krow_ld * SK + kc8) * 2);

    // V ldmatrix offsets
    const int krow = ((lane >> 3) & 1) * 8 + (lane & 7);
    const int ncol = (lane >> 4) * 8;
    const uint32_t offV = (uint32_t)((krow * SK + ncol) * 2);

    // Q fragments straight from gmem halves (scale pre-folded into K')
    uint32_t qh[4][4], ql[4][4];
    {
        const __half* qph = g_qkvh + (size_t)qrow0 * N3D + h * DH;
        const __half* qpl = g_qkvl + (size_t)qrow0 * N3D + h * DH;
#pragma unroll
        for (int ks = 0; ks < 4; ks++) {
            const int c = ks * 16 + 2 * tg;
            qh[ks][0] = *(const uint32_t*)(qph + (size_t)gid * N3D + c);
            qh[ks][1] = *(const uint32_t*)(qph + (size_t)(gid + 8) * N3D + c);
            qh[ks][2] = *(const uint32_t*)(qph + (size_t)gid * N3D + c + 8);
            qh[ks][3] = *(const uint32_t*)(qph + (size_t)(gid + 8) * N3D + c + 8);
            ql[ks][0] = *(const uint32_t*)(qpl + (size_t)gid * N3D + c);
            ql[ks][1] = *(const uint32_t*)(qpl + (size_t)(gid + 8) * N3D + c);
            ql[ks][2] = *(const uint32_t*)(qpl + (size_t)gid * N3D + c + 8);
            ql[ks][3] = *(const uint32_t*)(qpl + (size_t)(gid + 8) * N3D + c + 8);
        }
    }

    float o[8][4];
#pragma unroll
    for (int nt = 0; nt < 8; nt++)
#pragma unroll
        for (int i = 0; i < 4; i++) o[nt][i] = 0.f;
    float m0 = -1e30f, m1 = -1e30f, l0 = 0.f, l1 = 0.f;

    // prologue: tile 0
    cp16(saddr(Ksh[0]) + ksoff, g_qkvh + kgoff);
    cp16(saddr(Ksl[0]) + ksoff, g_qkvl + kgoff);
    cp16(saddr(Vsh[0]) + ksoff, g_qkvh + vgoff);
    cp16(saddr(Vsl[0]) + ksoff, g_qkvl + vgoff);
    cp_commit();

    const int niter = L / 32;
    for (int it = 0; it < niter; it++) {
        const int b = it & 1;
        if (it + 1 < niter) {
            const int nb = (it + 1) & 1;
            const size_t adv = (size_t)(it + 1) * 32 * N3D;
            cp16(saddr(Ksh[nb]) + ksoff, g_qkvh + kgoff + adv);
            cp16(saddr(Ksl[nb]) + ksoff, g_qkvl + kgoff + adv);
            cp16(saddr(Vsh[nb]) + ksoff, g_qkvh + vgoff + adv);
            cp16(saddr(Vsl[nb]) + ksoff, g_qkvl + vgoff + adv);
            cp_commit();
            cp_wait<1>();
        } else {
            cp_wait<0>();
        }
        __syncthreads();

        // S = Q @ K'^T  (16 x 32 per warp)
        float s[4][4];
#pragma unroll
        for (int nt = 0; nt < 4; nt++)
#pragma unroll
            for (int i = 0; i < 4; i++) s[nt][i] = 0.f;
        const __half* Khs = Ksh[b];
        const __half* Kls = Ksl[b];
#pragma unroll
        for (int ks = 0; ks < 4; ks++) {
            const int kc = ks * 16 + 2 * tg;
#pragma unroll
            for (int nt = 0; nt < 4; nt++) {
                const int rr = (nt * 8 + gid) * SK;
                uint32_t kh0 = *(const uint32_t*)(Khs + rr + kc);
                uint32_t kh1 = *(const uint32_t*)(Khs + rr + kc + 8);
                uint32_t kl0 = *(const uint32_t*)(Kls + rr + kc);
                uint32_t kl1 = *(const uint32_t*)(Kls + rr + kc + 8);
                mma_f16(s[nt], qh[ks], kh0, kh1);
                mma_f16(s[nt], qh[ks], kl0, kl1);
                mma_f16(s[nt], ql[ks], kh0, kh1);
            }
        }

        // online softmax
        float tm0 = -1e30f, tm1 = -1e30f;
#pragma unroll
        for (int nt = 0; nt < 4; nt++) {
            tm0 = fmaxf(tm0, fmaxf(s[nt][0], s[nt][1]));
            tm1 = fmaxf(tm1, fmaxf(s[nt][2], s[nt][3]));
        }
        tm0 = fmaxf(tm0, __shfl_xor_sync(0xffffffffu, tm0, 1));
        tm0 = fmaxf(tm0, __shfl_xor_sync(0xffffffffu, tm0, 2));
        tm1 = fmaxf(tm1, __shfl_xor_sync(0xffffffffu, tm1, 1));
        tm1 = fmaxf(tm1, __shfl_xor_sync(0xffffffffu, tm1, 2));
        const float nm0 = fmaxf(m0, tm0), nm1 = fmaxf(m1, tm1);
        const float r0 = __expf(m0 - nm0), r1 = __expf(m1 - nm1);
        m0 = nm0; m1 = nm1;
        l0 *= r0; l1 *= r1;
#pragma unroll
        for (int nt = 0; nt < 8; nt++) {
            o[nt][0] *= r0; o[nt][1] *= r0;
            o[nt][2] *= r1; o[nt][3] *= r1;
        }
#pragma unroll
        for (int nt = 0; nt < 4; nt++) {
            s[nt][0] = __expf(s[nt][0] - m0);
            s[nt][1] = __expf(s[nt][1] - m0);
            s[nt][2] = __expf(s[nt][2] - m1);
            s[nt][3] = __expf(s[nt][3] - m1);
            l0 += s[nt][0] + s[nt][1];
            l1 += s[nt][2] + s[nt][3];
        }

        // P @ V : P single fp16 term, V split
        const uint32_t vh_base = saddr(Vsh[b]) + offV;
        const uint32_t vl_base = saddr(Vsl[b]) + offV;
#pragma unroll
        for (int ks = 0; ks < 2; ks++) {
            uint32_t ah[4];
            ah[0] = cvt2(s[2 * ks][0],     s[2 * ks][1]);
            ah[1] = cvt2(s[2 * ks][2],     s[2 * ks][3]);
            ah[2] = cvt2(s[2 * ks + 1][0], s[2 * ks + 1][1]);
            ah[3] = cvt2(s[2 * ks + 1][2], s[2 * ks + 1][3]);
#pragma unroll
            for (int p = 0; p < 4; p++) {
                uint32_t Vfh[4], Vfl[4];
                const uint32_t vo = (uint32_t)(ks * 16 * SK * 2 + p * 32);
                ldsm_x4_t(Vfh, vh_base + vo);
                ldsm_x4_t(Vfl, vl_base + vo);
                mma_f16(o[2 * p],     ah, Vfh[0], Vfh[1]);
                mma_f16(o[2 * p],     ah, Vfl[0], Vfl[1]);
                mma_f16(o[2 * p + 1], ah, Vfh[2], Vfh[3]);
                mma_f16(o[2 * p + 1], ah, Vfl[2], Vfl[3]);
            }
        }
        __syncthreads();
    }

    l0 += __shfl_xor_sync(0xffffffffu, l0, 1);
    l0 += __shfl_xor_sync(0xffffffffu, l0, 2);
    l1 += __shfl_xor_sync(0xffffffffu, l1, 1);
    l1 += __shfl_xor_sync(0xffffffffu, l1, 2);
    const float inv0 = 1.f / l0, inv1 = 1.f / l1;

    // write ctx as split halves for the out GEMM
    __half* oph = g_ctxh + (size_t)qrow0 * D + h * DH;
    __half* opl = g_ctxl + (size_t)qrow0 * D + h * DH;
#pragma unroll
    for (int nt = 0; nt < 8; nt++) {
        const int col = nt * 8 + 2 * tg;
        uint32_t hh, ll;
        split2(o[nt][0] * inv0, o[nt][1] * inv0, hh, ll);
        *(uint32_t*)(oph + (size_t)gid * D + col) = hh;
        *(uint32_t*)(opl + (size_t)gid * D + col) = ll;
        split2(o[nt][2] * inv1, o[nt][3] * inv1, hh, ll);
        *(uint32_t*)(oph + (size_t)(gid + 8) * D + col) = hh;
        *(uint32_t*)(opl + (size_t)(gid + 8) * D + col) = ll;
    }
}

// ---------------------------------------------------------------------------
extern "C" void kernel_launch(void* const* d_in, const int* in_sizes, int n_in,
                              void* d_out, int out_size)
{
    const float* x    = (const float*)d_in[0];
    const float* Wqkv = (const float*)d_in[1];
    const float* bqkv = (const float*)d_in[2];
    const float* Wout = (const float*)d_in[3];
    const float* bout = (const float*)d_in[4];
    const float* rel  = (const float*)d_in[5];
    float* out = (float*)d_out;

    __half *xh, *xl, *wqh, *wql, *woh, *wol, *qkvh, *qkvl, *ctxh, *ctxl;
    { void* p; cudaGetSymbolAddress(&p, g_xh);   xh   = (__half*)p; }
    { void* p; cudaGetSymbolAddress(&p, g_xl);   xl   = (__half*)p; }
    { void* p; cudaGetSymbolAddress(&p, g_wqh);  wqh  = (__half*)p; }
    { void* p; cudaGetSymbolAddress(&p, g_wql);  wql  = (__half*)p; }
    { void* p; cudaGetSymbolAddress(&p, g_woh);  woh  = (__half*)p; }
    { void* p; cudaGetSymbolAddress(&p, g_wol);  wol  = (__half*)p; }
    { void* p; cudaGetSymbolAddress(&p, g_qkvh); qkvh = (__half*)p; }
    { void* p; cudaGetSymbolAddress(&p, g_qkvl); qkvl = (__half*)p; }
    { void* p; cudaGetSymbolAddress(&p, g_ctxh); ctxh = (__half*)p; }
    { void* p; cudaGetSymbolAddress(&p, g_ctxl); ctxl = (__half*)p; }

    // 0) split inputs
    split_kernel<<<(L * D / 4) / 256, 256>>>(x, xh, xl, L * D / 4);
    split_kernel<<<(D * N3D / 4) / 256, 256>>>(Wqkv, wqh, wql, D * N3D / 4);
    split_kernel<<<(D * D / 4) / 256, 256>>>(Wout, woh, wol, D * D / 4);

    // 1) qkv = x @ Wqkv + bqkv (split output; rel fold + scale on K' section)
    {
        dim3 grid(N3D / 128, L / 128);
        gemm_f16p<<<grid, 256>>>(xh, xl, wqh, wql, bqkv,
                                 nullptr, qkvh, qkvl, L, N3D, D, rel);
    }
    // 2) flash attention
    {
        dim3 grid(L / 128, H);
        flash_f16p<<<grid, 256>>>();
    }
    // 3) out = ctx @ Wout + bout (fp32 output)
    {
        dim3 grid(D / 128, L / 128);
        gemm_f16p<<<grid, 256>>>(ctxh, ctxl, woh, wol, bout,
                                 out, nullptr, nullptr, L, D, D, nullptr);
    }
}

// round 5
// speedup vs baseline: 4.3490x; 1.1135x over previous
#include <cuda_runtime.h>
#include <cuda_fp16.h>
#include <cstdint>

#define L    2048
#define D    1024
#define H    16
#define DH   64
#define N3D  3072
#define SCALE 0.125f

// Scratch (device globals — no allocation allowed)
__device__ __half g_xh[L * D],     g_xl[L * D];
__device__ __half g_wqh[D * N3D],  g_wql[D * N3D];
__device__ __half g_woh[D * D],    g_wol[D * D];
__device__ __half g_qkvh[L * N3D], g_qkvl[L * N3D];   // q | k'(rel+scale folded) | v
__device__ __half g_ctxh[L * D],   g_ctxl[L * D];

// ---------------------------------------------------------------------------
// helpers
// ---------------------------------------------------------------------------
__device__ __forceinline__ uint32_t cvt2(float x, float y) {
    __half2 h = __float22half2_rn(make_float2(x, y));
    return *(uint32_t*)&h;
}
__device__ __forceinline__ void split2(float x, float y, uint32_t& hi, uint32_t& lo) {
    __half2 h = __float22half2_rn(make_float2(x, y));
    float2 hf = __half22float2(h);
    hi = *(uint32_t*)&h;
    lo = cvt2(x - hf.x, y - hf.y);
}
__device__ __forceinline__ void mma_f16(float* d, const uint32_t* a, uint32_t b0, uint32_t b1) {
    asm volatile(
        "mma.sync.aligned.m16n8k16.row.col.f32.f16.f16.f32 "
        "{%0,%1,%2,%3},{%4,%5,%6,%7},{%8,%9},{%0,%1,%2,%3};\n"
        : "+f"(d[0]), "+f"(d[1]), "+f"(d[2]), "+f"(d[3])
        : "r"(a[0]), "r"(a[1]), "r"(a[2]), "r"(a[3]), "r"(b0), "r"(b1));
}
__device__ __forceinline__ void ldsm_x4(uint32_t* r, uint32_t addr) {
    asm volatile("ldmatrix.sync.aligned.m8n8.x4.shared.b16 {%0,%1,%2,%3},[%4];\n"
                 : "=r"(r[0]), "=r"(r[1]), "=r"(r[2]), "=r"(r[3]) : "r"(addr));
}
__device__ __forceinline__ void ldsm_x4_t(uint32_t* r, uint32_t addr) {
    asm volatile("ldmatrix.sync.aligned.m8n8.x4.trans.shared.b16 {%0,%1,%2,%3},[%4];\n"
                 : "=r"(r[0]), "=r"(r[1]), "=r"(r[2]), "=r"(r[3]) : "r"(addr));
}
__device__ __forceinline__ uint32_t saddr(const void* p) {
    return (uint32_t)__cvta_generic_to_shared(p);
}
__device__ __forceinline__ void cp16(uint32_t s, const void* g) {
    asm volatile("cp.async.cg.shared.global [%0],[%1],16;\n" :: "r"(s), "l"(g));
}
__device__ __forceinline__ void cp_commit() { asm volatile("cp.async.commit_group;\n"); }
template <int N> __device__ __forceinline__ void cp_wait() {
    asm volatile("cp.async.wait_group %0;\n" :: "n"(N));
}

// ---------------------------------------------------------------------------
// one-pass fp32 -> (hi,lo) split
// ---------------------------------------------------------------------------
__global__ __launch_bounds__(256) void split_kernel(
    const float* __restrict__ src, __half* __restrict__ hi, __half* __restrict__ lo, int n4)
{
    int i = blockIdx.x * 256 + threadIdx.x;
    if (i < n4) {
        float4 f = ((const float4*)src)[i];
        uint32_t h0, l0, h1, l1;
        split2(f.x, f.y, h0, l0);
        split2(f.z, f.w, h1, l1);
        ((uint2*)hi)[i] = make_uint2(h0, h1);
        ((uint2*)lo)[i] = make_uint2(l0, l1);
    }
}

// ---------------------------------------------------------------------------
// split-fp16 GEMM: 3-stage cp.async, ONE barrier/iter, BK=16, tile 128x128,
// dynamic smem. 256 thr, warps 4(m)x2(n).
// ---------------------------------------------------------------------------
#define SA 24
#define SB 136
#define ASTG (128 * SA)   // halves per A stage (per hi/lo)
#define BSTG (16 * SB)    // halves per B stage (per hi/lo)
#define GEMM_SMEM_BYTES (3 * (ASTG + BSTG) * 2 * 2)

__global__ __launch_bounds__(256, 2) void gemm_f16p(
    const __half* __restrict__ Ah, const __half* __restrict__ Al,
    const __half* __restrict__ Bh, const __half* __restrict__ Bl,
    const float* __restrict__ bias,
    float* __restrict__ Cf, __half* __restrict__ Ch, __half* __restrict__ Cl,
    int M, int N, int K, const float* __restrict__ rel)
{
    extern __shared__ __align__(16) __half dsm[];
    __half* Ash = dsm;                    // [3][ASTG]
    __half* Asl = Ash + 3 * ASTG;
    __half* Bsh = Asl + 3 * ASTG;         // [3][BSTG]
    __half* Bsl = Bsh + 3 * BSTG;

    const int tid = threadIdx.x;
    const int warp = tid >> 5, lane = tid & 31;
    const int gid = lane >> 2, tg = lane & 3;
    const int bm = blockIdx.y * 128, bn = blockIdx.x * 128;
    const int wm = (warp >> 1) * 32, wn = (warp & 1) * 64;

    float acc[2][8][4];
#pragma unroll
    for (int mt = 0; mt < 2; mt++)
#pragma unroll
        for (int nt = 0; nt < 8; nt++)
#pragma unroll
            for (int i = 0; i < 4; i++) acc[mt][nt][i] = 0.f;

    // cp.async indices
    const int arow = tid >> 1, ac = (tid & 1) * 8;
    const int brow = tid >> 4, bc = (tid & 15) * 8;
    const size_t agoff = (size_t)(bm + arow) * K + ac;
    const size_t bgoff = (size_t)brow * N + bn + bc;
    const uint32_t asoff = (uint32_t)((arow * SA + ac) * 2);
    const uint32_t bsoff = (uint32_t)((brow * SB + bc) * 2);

    // ldmatrix lane offsets
    const int l15 = lane & 15, lhi = lane >> 4;
    const int krow = ((lane >> 3) & 1) * 8 + (lane & 7);
    const uint32_t offA = (uint32_t)(((wm + l15) * SA + lhi * 8) * 2);
    const uint32_t offB = (uint32_t)((krow * SB + wn + lhi * 8) * 2);

    const int nkt = K >> 4;   // >= 3 always here

    // prologue: stages 0 and 1
#pragma unroll
    for (int s = 0; s < 2; s++) {
        const size_t ka = agoff + s * 16;
        const size_t kb = bgoff + (size_t)s * 16 * N;
        cp16(saddr(Ash + s * ASTG) + asoff, Ah + ka);
        cp16(saddr(Asl + s * ASTG) + asoff, Al + ka);
        cp16(saddr(Bsh + s * BSTG) + bsoff, Bh + kb);
        cp16(saddr(Bsl + s * BSTG) + bsoff, Bl + kb);
        cp_commit();
    }

    for (int kt = 0; kt < nkt; kt++) {
        const int b = kt % 3;
        if (kt == nkt - 1) cp_wait<0>(); else cp_wait<1>();
        __syncthreads();
        if (kt + 2 < nkt) {
            const int s2 = (kt + 2) % 3;
            const size_t ka = agoff + (size_t)(kt + 2) * 16;
            const size_t kb = bgoff + (size_t)(kt + 2) * 16 * N;
            cp16(saddr(Ash + s2 * ASTG) + asoff, Ah + ka);
            cp16(saddr(Asl + s2 * ASTG) + asoff, Al + ka);
            cp16(saddr(Bsh + s2 * BSTG) + bsoff, Bh + kb);
            cp16(saddr(Bsl + s2 * BSTG) + bsoff, Bl + kb);
            cp_commit();
        }

        uint32_t Afh[2][4], Afl[2][4];
        const uint32_t ah_base = saddr(Ash + b * ASTG) + offA;
        const uint32_t al_base = saddr(Asl + b * ASTG) + offA;
#pragma unroll
        for (int mt = 0; mt < 2; mt++) {
            ldsm_x4(Afh[mt], ah_base + mt * 16 * SA * 2);
            ldsm_x4(Afl[mt], al_base + mt * 16 * SA * 2);
        }
        const uint32_t bh_base = saddr(Bsh + b * BSTG) + offB;
        const uint32_t bl_base = saddr(Bsl + b * BSTG) + offB;
#pragma unroll
        for (int p = 0; p < 4; p++) {
            uint32_t Bfh[4], Bfl[4];
            ldsm_x4_t(Bfh, bh_base + p * 32);
            ldsm_x4_t(Bfl, bl_base + p * 32);
#pragma unroll
            for (int mt = 0; mt < 2; mt++) {
                mma_f16(acc[mt][2 * p],     Afh[mt], Bfh[0], Bfh[1]);
                mma_f16(acc[mt][2 * p],     Afh[mt], Bfl[0], Bfl[1]);
                mma_f16(acc[mt][2 * p],     Afl[mt], Bfh[0], Bfh[1]);
                mma_f16(acc[mt][2 * p + 1], Afh[mt], Bfh[2], Bfh[3]);
                mma_f16(acc[mt][2 * p + 1], Afh[mt], Bfl[2], Bfl[3]);
                mma_f16(acc[mt][2 * p + 1], Afl[mt], Bfh[2], Bfh[3]);
            }
        }
    }

    // epilogue
#pragma unroll
    for (int mt = 0; mt < 2; mt++) {
#pragma unroll
        for (int nt = 0; nt < 8; nt++) {
            const int col = bn + wn + nt * 8 + 2 * tg;
            const float bi0 = bias[col], bi1 = bias[col + 1];
#pragma unroll
            for (int hf = 0; hf < 2; hf++) {
                const int row = bm + wm + mt * 16 + gid + hf * 8;
                float v0 = acc[mt][nt][hf * 2 + 0] + bi0;
                float v1 = acc[mt][nt][hf * 2 + 1] + bi1;
                if (Ch != nullptr) {
                    if (col >= 1024 && col < 2048) {       // K' section
                        if (row >= 1) {
                            v0 += rel[(size_t)(row - 1) * 64 + (col & 63)];
                            v1 += rel[(size_t)(row - 1) * 64 + ((col + 1) & 63)];
                        }
                        v0 *= SCALE; v1 *= SCALE;          // exact pow2
                    }
                    uint32_t hh, ll;
                    split2(v0, v1, hh, ll);
                    *(uint32_t*)(Ch + (size_t)row * N + col) = hh;
                    *(uint32_t*)(Cl + (size_t)row * N + col) = ll;
                } else {
                    *(float2*)(Cf + (size_t)row * N + col) = make_float2(v0, v1);
                }
            }
        }
    }
}

// ---------------------------------------------------------------------------
// Flash attention: 3-stage cp.async, one barrier/iter, 32-key tiles,
// K fragments via ldsm.x4, V single fp16 term. 256 thr / 128 q-rows.
// grid = (L/128, H)
// ---------------------------------------------------------------------------
#define SK 72

__global__ __launch_bounds__(256, 2) void flash_f16p()
{
    __shared__ __align__(16) __half Ksh[3][32 * SK], Ksl[3][32 * SK], Vsh[3][32 * SK];

    const int h = blockIdx.y;
    const int tid = threadIdx.x;
    const int warp = tid >> 5, lane = tid & 31;
    const int gid = lane >> 2, tg = lane & 3;
    const int qrow0 = blockIdx.x * 128 + warp * 16;

    // cp.async indices: 32 rows x 8 chunks per array
    const int krow_ld = tid >> 3, kc8 = (tid & 7) * 8;
    const size_t kgoff = (size_t)krow_ld * N3D + D + h * DH + kc8;       // K'
    const size_t vgoff = kgoff + D;                                      // V
    const uint32_t ksoff = (uint32_t)((krow_ld * SK + kc8) * 2);

    // K ldsm (non-trans) lane offsets: lanes 0-7 n0-7/k0, 8-15 n0-7/k8,
    // 16-23 n8-15/k0, 24-31 n8-15/k8
    const int kr_lane = (lane & 7) + ((lane >> 4) & 1) * 8;
    const int kc_lane = ((lane >> 3) & 1) * 8;
    const uint32_t offK = (uint32_t)((kr_lane * SK + kc_lane) * 2);
    // V ldsm (trans) lane offsets
    const int vrow = ((lane >> 3) & 1) * 8 + (lane & 7);
    const int vcol = (lane >> 4) * 8;
    const uint32_t offV = (uint32_t)((vrow * SK + vcol) * 2);

    // Q fragments straight from gmem halves (scale folded into K')
    uint32_t qh[4][4], ql[4][4];
    {
        const __half* qph = g_qkvh + (size_t)qrow0 * N3D + h * DH;
        const __half* qpl = g_qkvl + (size_t)qrow0 * N3D + h * DH;
#pragma unroll
        for (int ks = 0; ks < 4; ks++) {
            const int c = ks * 16 + 2 * tg;
            qh[ks][0] = *(const uint32_t*)(qph + (size_t)gid * N3D + c);
            qh[ks][1] = *(const uint32_t*)(qph + (size_t)(gid + 8) * N3D + c);
            qh[ks][2] = *(const uint32_t*)(qph + (size_t)gid * N3D + c + 8);
            qh[ks][3] = *(const uint32_t*)(qph + (size_t)(gid + 8) * N3D + c + 8);
            ql[ks][0] = *(const uint32_t*)(qpl + (size_t)gid * N3D + c);
            ql[ks][1] = *(const uint32_t*)(qpl + (size_t)(gid + 8) * N3D + c);
            ql[ks][2] = *(const uint32_t*)(qpl + (size_t)gid * N3D + c + 8);
            ql[ks][3] = *(const uint32_t*)(qpl + (size_t)(gid + 8) * N3D + c + 8);
        }
    }

    float o[8][4];
#pragma unroll
    for (int nt = 0; nt < 8; nt++)
#pragma unroll
        for (int i = 0; i < 4; i++) o[nt][i] = 0.f;
    float m0 = -1e30f, m1 = -1e30f, l0 = 0.f, l1 = 0.f;

    // prologue: tiles 0,1
#pragma unroll
    for (int s = 0; s < 2; s++) {
        const size_t adv = (size_t)s * 32 * N3D;
        cp16(saddr(Ksh[s]) + ksoff, g_qkvh + kgoff + adv);
        cp16(saddr(Ksl[s]) + ksoff, g_qkvl + kgoff + adv);
        cp16(saddr(Vsh[s]) + ksoff, g_qkvh + vgoff + adv);
        cp_commit();
    }

    const int niter = L / 32;
    for (int it = 0; it < niter; it++) {
        const int b = it % 3;
        if (it == niter - 1) cp_wait<0>(); else cp_wait<1>();
        __syncthreads();
        if (it + 2 < niter) {
            const int s2 = (it + 2) % 3;
            const size_t adv = (size_t)(it + 2) * 32 * N3D;
            cp16(saddr(Ksh[s2]) + ksoff, g_qkvh + kgoff + adv);
            cp16(saddr(Ksl[s2]) + ksoff, g_qkvl + kgoff + adv);
            cp16(saddr(Vsh[s2]) + ksoff, g_qkvh + vgoff + adv);
            cp_commit();
        }

        // S = Q @ K'^T  (16 x 32 per warp)
        float s[4][4];
#pragma unroll
        for (int nt = 0; nt < 4; nt++)
#pragma unroll
            for (int i = 0; i < 4; i++) s[nt][i] = 0.f;
        const uint32_t kh_base = saddr(Ksh[b]) + offK;
        const uint32_t kl_base = saddr(Ksl[b]) + offK;
#pragma unroll
        for (int ks = 0; ks < 4; ks++) {
#pragma unroll
            for (int ntp = 0; ntp < 2; ntp++) {
                uint32_t Kh[4], Kl[4];
                const uint32_t off = (uint32_t)((ntp * 16 * SK + ks * 16) * 2);
                ldsm_x4(Kh, kh_base + off);
                ldsm_x4(Kl, kl_base + off);
                mma_f16(s[2 * ntp],     qh[ks], Kh[0], Kh[1]);
                mma_f16(s[2 * ntp],     qh[ks], Kl[0], Kl[1]);
                mma_f16(s[2 * ntp],     ql[ks], Kh[0], Kh[1]);
                mma_f16(s[2 * ntp + 1], qh[ks], Kh[2], Kh[3]);
                mma_f16(s[2 * ntp + 1], qh[ks], Kl[2], Kl[3]);
                mma_f16(s[2 * ntp + 1], ql[ks], Kh[2], Kh[3]);
            }
        }

        // online softmax
        float tm0 = -1e30f, tm1 = -1e30f;
#pragma unroll
        for (int nt = 0; nt < 4; nt++) {
            tm0 = fmaxf(tm0, fmaxf(s[nt][0], s[nt][1]));
            tm1 = fmaxf(tm1, fmaxf(s[nt][2], s[nt][3]));
        }
        tm0 = fmaxf(tm0, __shfl_xor_sync(0xffffffffu, tm0, 1));
        tm0 = fmaxf(tm0, __shfl_xor_sync(0xffffffffu, tm0, 2));
        tm1 = fmaxf(tm1, __shfl_xor_sync(0xffffffffu, tm1, 1));
        tm1 = fmaxf(tm1, __shfl_xor_sync(0xffffffffu, tm1, 2));
        const float nm0 = fmaxf(m0, tm0), nm1 = fmaxf(m1, tm1);
        const float r0 = __expf(m0 - nm0), r1 = __expf(m1 - nm1);
        m0 = nm0; m1 = nm1;
        l0 *= r0; l1 *= r1;
#pragma unroll
        for (int nt = 0; nt < 8; nt++) {
            o[nt][0] *= r0; o[nt][1] *= r0;
            o[nt][2] *= r1; o[nt][3] *= r1;
        }
#pragma unroll
        for (int nt = 0; nt < 4; nt++) {
            s[nt][0] = __expf(s[nt][0] - m0);
            s[nt][1] = __expf(s[nt][1] - m0);
            s[nt][2] = __expf(s[nt][2] - m1);
            s[nt][3] = __expf(s[nt][3] - m1);
            l0 += s[nt][0] + s[nt][1];
            l1 += s[nt][2] + s[nt][3];
        }

        // P @ V : P single fp16 term, V single fp16 term
        const uint32_t vh_base = saddr(Vsh[b]) + offV;
#pragma unroll
        for (int ks = 0; ks < 2; ks++) {
            uint32_t ah[4];
            ah[0] = cvt2(s[2 * ks][0],     s[2 * ks][1]);
            ah[1] = cvt2(s[2 * ks][2],     s[2 * ks][3]);
            ah[2] = cvt2(s[2 * ks + 1][0], s[2 * ks + 1][1]);
            ah[3] = cvt2(s[2 * ks + 1][2], s[2 * ks + 1][3]);
#pragma unroll
            for (int p = 0; p < 4; p++) {
                uint32_t Vf[4];
                ldsm_x4_t(Vf, vh_base + (uint32_t)((ks * 16 * SK + p * 16) * 2));
                mma_f16(o[2 * p],     ah, Vf[0], Vf[1]);
                mma_f16(o[2 * p + 1], ah, Vf[2], Vf[3]);
            }
        }
    }

    l0 += __shfl_xor_sync(0xffffffffu, l0, 1);
    l0 += __shfl_xor_sync(0xffffffffu, l0, 2);
    l1 += __shfl_xor_sync(0xffffffffu, l1, 1);
    l1 += __shfl_xor_sync(0xffffffffu, l1, 2);
    const float inv0 = 1.f / l0, inv1 = 1.f / l1;

    // write ctx as split halves for the out GEMM
    __half* oph = g_ctxh + (size_t)qrow0 * D + h * DH;
    __half* opl = g_ctxl + (size_t)qrow0 * D + h * DH;
#pragma unroll
    for (int nt = 0; nt < 8; nt++) {
        const int col = nt * 8 + 2 * tg;
        uint32_t hh, ll;
        split2(o[nt][0] * inv0, o[nt][1] * inv0, hh, ll);
        *(uint32_t*)(oph + (size_t)gid * D + col) = hh;
        *(uint32_t*)(opl + (size_t)gid * D + col) = ll;
        split2(o[nt][2] * inv1, o[nt][3] * inv1, hh, ll);
        *(uint32_t*)(oph + (size_t)(gid + 8) * D + col) = hh;
        *(uint32_t*)(opl + (size_t)(gid + 8) * D + col) = ll;
    }
}

// ---------------------------------------------------------------------------
extern "C" void kernel_launch(void* const* d_in, const int* in_sizes, int n_in,
                              void* d_out, int out_size)
{
    const float* x    = (const float*)d_in[0];
    const float* Wqkv = (const float*)d_in[1];
    const float* bqkv = (const float*)d_in[2];
    const float* Wout = (const float*)d_in[3];
    const float* bout = (const float*)d_in[4];
    const float* rel  = (const float*)d_in[5];
    float* out = (float*)d_out;

    __half *xh, *xl, *wqh, *wql, *woh, *wol, *qkvh, *qkvl, *ctxh, *ctxl;
    { void* p; cudaGetSymbolAddress(&p, g_xh);   xh   = (__half*)p; }
    { void* p; cudaGetSymbolAddress(&p, g_xl);   xl   = (__half*)p; }
    { void* p; cudaGetSymbolAddress(&p, g_wqh);  wqh  = (__half*)p; }
    { void* p; cudaGetSymbolAddress(&p, g_wql);  wql  = (__half*)p; }
    { void* p; cudaGetSymbolAddress(&p, g_woh);  woh  = (__half*)p; }
    { void* p; cudaGetSymbolAddress(&p, g_wol);  wol  = (__half*)p; }
    { void* p; cudaGetSymbolAddress(&p, g_qkvh); qkvh = (__half*)p; }
    { void* p; cudaGetSymbolAddress(&p, g_qkvl); qkvl = (__half*)p; }
    { void* p; cudaGetSymbolAddress(&p, g_ctxh); ctxh = (__half*)p; }
    { void* p; cudaGetSymbolAddress(&p, g_ctxl); ctxl = (__half*)p; }

    cudaFuncSetAttribute(gemm_f16p, cudaFuncAttributeMaxDynamicSharedMemorySize,
                         GEMM_SMEM_BYTES);

    // 0) split inputs
    split_kernel<<<(L * D / 4) / 256, 256>>>(x, xh, xl, L * D / 4);
    split_kernel<<<(D * N3D / 4) / 256, 256>>>(Wqkv, wqh, wql, D * N3D / 4);
    split_kernel<<<(D * D / 4) / 256, 256>>>(Wout, woh, wol, D * D / 4);

    // 1) qkv = x @ Wqkv + bqkv (split output; rel fold + scale on K' section)
    {
        dim3 grid(N3D / 128, L / 128);
        gemm_f16p<<<grid, 256, GEMM_SMEM_BYTES>>>(xh, xl, wqh, wql, bqkv,
                                 nullptr, qkvh, qkvl, L, N3D, D, rel);
    }
    // 2) flash attention
    {
        dim3 grid(L / 128, H);
        flash_f16p<<<grid, 256>>>();
    }
    // 3) out = ctx @ Wout + bout (fp32 output)
    {
        dim3 grid(D / 128, L / 128);
        gemm_f16p<<<grid, 256, GEMM_SMEM_BYTES>>>(ctxh, ctxl, woh, wol, bout,
                                 out, nullptr, nullptr, L, D, D, nullptr);
    }
}

// round 6
// speedup vs baseline: 5.6343x; 1.2955x over previous
#include <cuda_runtime.h>
#include <cuda_fp16.h>
#include <cstdint>

#define L    2048
#define D    1024
#define H    16
#define DH   64
#define N3D  3072
#define SCALE 0.125f

// Scratch (device globals — no allocation allowed)
__device__ __half g_xh[L * D];
__device__ __half g_wqh[D * N3D],  g_wql[D * N3D];
__device__ __half g_woh[D * D],    g_wol[D * D];
__device__ __half g_qkvh[L * N3D];                 // q | k'(rel+scale folded) | v
__device__ __half g_qkvl[L * N3D];                 // only K' section is ever read
__device__ __half g_ctxh[L * D];

// ---------------------------------------------------------------------------
// helpers
// ---------------------------------------------------------------------------
__device__ __forceinline__ uint32_t cvt2(float x, float y) {
    __half2 h = __float22half2_rn(make_float2(x, y));
    return *(uint32_t*)&h;
}
__device__ __forceinline__ void split2(float x, float y, uint32_t& hi, uint32_t& lo) {
    __half2 h = __float22half2_rn(make_float2(x, y));
    float2 hf = __half22float2(h);
    hi = *(uint32_t*)&h;
    lo = cvt2(x - hf.x, y - hf.y);
}
__device__ __forceinline__ void mma_f16(float* d, const uint32_t* a, uint32_t b0, uint32_t b1) {
    asm volatile(
        "mma.sync.aligned.m16n8k16.row.col.f32.f16.f16.f32 "
        "{%0,%1,%2,%3},{%4,%5,%6,%7},{%8,%9},{%0,%1,%2,%3};\n"
        : "+f"(d[0]), "+f"(d[1]), "+f"(d[2]), "+f"(d[3])
        : "r"(a[0]), "r"(a[1]), "r"(a[2]), "r"(a[3]), "r"(b0), "r"(b1));
}
__device__ __forceinline__ void ldsm_x4(uint32_t* r, uint32_t addr) {
    asm volatile("ldmatrix.sync.aligned.m8n8.x4.shared.b16 {%0,%1,%2,%3},[%4];\n"
                 : "=r"(r[0]), "=r"(r[1]), "=r"(r[2]), "=r"(r[3]) : "r"(addr));
}
__device__ __forceinline__ void ldsm_x4_t(uint32_t* r, uint32_t addr) {
    asm volatile("ldmatrix.sync.aligned.m8n8.x4.trans.shared.b16 {%0,%1,%2,%3},[%4];\n"
                 : "=r"(r[0]), "=r"(r[1]), "=r"(r[2]), "=r"(r[3]) : "r"(addr));
}
__device__ __forceinline__ uint32_t saddr(const void* p) {
    return (uint32_t)__cvta_generic_to_shared(p);
}
__device__ __forceinline__ void cp16(uint32_t s, const void* g) {
    asm volatile("cp.async.cg.shared.global [%0],[%1],16;\n" :: "r"(s), "l"(g));
}
__device__ __forceinline__ void cp_commit() { asm volatile("cp.async.commit_group;\n"); }
template <int N> __device__ __forceinline__ void cp_wait() {
    asm volatile("cp.async.wait_group %0;\n" :: "n"(N));
}

// ---------------------------------------------------------------------------
// fp32 -> (hi,lo) split  /  fp32 -> hi convert
// ---------------------------------------------------------------------------
__global__ __launch_bounds__(256) void split_kernel(
    const float* __restrict__ src, __half* __restrict__ hi, __half* __restrict__ lo, int n4)
{
    int i = blockIdx.x * 256 + threadIdx.x;
    if (i < n4) {
        float4 f = ((const float4*)src)[i];
        uint32_t h0, l0, h1, l1;
        split2(f.x, f.y, h0, l0);
        split2(f.z, f.w, h1, l1);
        ((uint2*)hi)[i] = make_uint2(h0, h1);
        ((uint2*)lo)[i] = make_uint2(l0, l1);
    }
}
__global__ __launch_bounds__(256) void cvt_kernel(
    const float* __restrict__ src, __half* __restrict__ hi, int n4)
{
    int i = blockIdx.x * 256 + threadIdx.x;
    if (i < n4) {
        float4 f = ((const float4*)src)[i];
        ((uint2*)hi)[i] = make_uint2(cvt2(f.x, f.y), cvt2(f.z, f.w));
    }
}

// ---------------------------------------------------------------------------
// GEMM: C = A_hi[M,K] @ (B_hi + B_lo)[K,N] + bias. A hi-only (2 products).
// 3-stage cp.async, one barrier/iter, BK=16, tile 128x128, 256 thr.
// Ch!=null: split output; lo written only for K' cols [1024,2048) which also
// get rel fold + 0.125 scale. Else fp32 to Cf.
// ---------------------------------------------------------------------------
#define SA 24
#define SB 136
#define ASTG (128 * SA)
#define BSTG (16 * SB)
#define GEMM_SMEM_BYTES ((3 * ASTG + 2 * 3 * BSTG) * 2)

__global__ __launch_bounds__(256, 2) void gemm_f16p(
    const __half* __restrict__ Ah,
    const __half* __restrict__ Bh, const __half* __restrict__ Bl,
    const float* __restrict__ bias,
    float* __restrict__ Cf, __half* __restrict__ Ch, __half* __restrict__ Cl,
    int M, int N, int K, const float* __restrict__ rel)
{
    extern __shared__ __align__(16) __half dsm[];
    __half* Ash = dsm;                    // [3][ASTG]
    __half* Bsh = Ash + 3 * ASTG;         // [3][BSTG]
    __half* Bsl = Bsh + 3 * BSTG;

    const int tid = threadIdx.x;
    const int warp = tid >> 5, lane = tid & 31;
    const int gid = lane >> 2, tg = lane & 3;
    const int bm = blockIdx.y * 128, bn = blockIdx.x * 128;
    const int wm = (warp >> 1) * 32, wn = (warp & 1) * 64;

    float acc[2][8][4];
#pragma unroll
    for (int mt = 0; mt < 2; mt++)
#pragma unroll
        for (int nt = 0; nt < 8; nt++)
#pragma unroll
            for (int i = 0; i < 4; i++) acc[mt][nt][i] = 0.f;

    const int arow = tid >> 1, ac = (tid & 1) * 8;
    const int brow = tid >> 4, bc = (tid & 15) * 8;
    const size_t agoff = (size_t)(bm + arow) * K + ac;
    const size_t bgoff = (size_t)brow * N + bn + bc;
    const uint32_t asoff = (uint32_t)((arow * SA + ac) * 2);
    const uint32_t bsoff = (uint32_t)((brow * SB + bc) * 2);

    const int l15 = lane & 15, lhi = lane >> 4;
    const int krow = ((lane >> 3) & 1) * 8 + (lane & 7);
    const uint32_t offA = (uint32_t)(((wm + l15) * SA + lhi * 8) * 2);
    const uint32_t offB = (uint32_t)((krow * SB + wn + lhi * 8) * 2);

    const int nkt = K >> 4;

#pragma unroll
    for (int s = 0; s < 2; s++) {
        const size_t ka = agoff + s * 16;
        const size_t kb = bgoff + (size_t)s * 16 * N;
        cp16(saddr(Ash + s * ASTG) + asoff, Ah + ka);
        cp16(saddr(Bsh + s * BSTG) + bsoff, Bh + kb);
        cp16(saddr(Bsl + s * BSTG) + bsoff, Bl + kb);
        cp_commit();
    }

    for (int kt = 0; kt < nkt; kt++) {
        const int b = kt % 3;
        if (kt == nkt - 1) cp_wait<0>(); else cp_wait<1>();
        __syncthreads();
        if (kt + 2 < nkt) {
            const int s2 = (kt + 2) % 3;
            const size_t ka = agoff + (size_t)(kt + 2) * 16;
            const size_t kb = bgoff + (size_t)(kt + 2) * 16 * N;
            cp16(saddr(Ash + s2 * ASTG) + asoff, Ah + ka);
            cp16(saddr(Bsh + s2 * BSTG) + bsoff, Bh + kb);
            cp16(saddr(Bsl + s2 * BSTG) + bsoff, Bl + kb);
            cp_commit();
        }

        uint32_t Af[2][4];
        const uint32_t ah_base = saddr(Ash + b * ASTG) + offA;
#pragma unroll
        for (int mt = 0; mt < 2; mt++)
            ldsm_x4(Af[mt], ah_base + mt * 16 * SA * 2);

        const uint32_t bh_base = saddr(Bsh + b * BSTG) + offB;
        const uint32_t bl_base = saddr(Bsl + b * BSTG) + offB;
#pragma unroll
        for (int p = 0; p < 4; p++) {
            uint32_t Bfh[4], Bfl[4];
            ldsm_x4_t(Bfh, bh_base + p * 32);
            ldsm_x4_t(Bfl, bl_base + p * 32);
#pragma unroll
            for (int mt = 0; mt < 2; mt++) {
                mma_f16(acc[mt][2 * p],     Af[mt], Bfh[0], Bfh[1]);
                mma_f16(acc[mt][2 * p],     Af[mt], Bfl[0], Bfl[1]);
                mma_f16(acc[mt][2 * p + 1], Af[mt], Bfh[2], Bfh[3]);
                mma_f16(acc[mt][2 * p + 1], Af[mt], Bfl[2], Bfl[3]);
            }
        }
    }

    // epilogue
#pragma unroll
    for (int mt = 0; mt < 2; mt++) {
#pragma unroll
        for (int nt = 0; nt < 8; nt++) {
            const int col = bn + wn + nt * 8 + 2 * tg;
            const float bi0 = bias[col], bi1 = bias[col + 1];
            const bool kcol = (col >= 1024) && (col < 2048);
#pragma unroll
            for (int hf = 0; hf < 2; hf++) {
                const int row = bm + wm + mt * 16 + gid + hf * 8;
                float v0 = acc[mt][nt][hf * 2 + 0] + bi0;
                float v1 = acc[mt][nt][hf * 2 + 1] + bi1;
                if (Ch != nullptr) {
                    if (kcol) {                            // K' section
                        if (row >= 1) {
                            v0 += rel[(size_t)(row - 1) * 64 + (col & 63)];
                            v1 += rel[(size_t)(row - 1) * 64 + ((col + 1) & 63)];
                        }
                        v0 *= SCALE; v1 *= SCALE;          // exact pow2
                        uint32_t hh, ll;
                        split2(v0, v1, hh, ll);
                        *(uint32_t*)(Ch + (size_t)row * N + col) = hh;
                        *(uint32_t*)(Cl + (size_t)row * N + col) = ll;
                    } else {
                        *(uint32_t*)(Ch + (size_t)row * N + col) = cvt2(v0, v1);
                    }
                } else {
                    *(float2*)(Cf + (size_t)row * N + col) = make_float2(v0, v1);
                }
            }
        }
    }
}

// ---------------------------------------------------------------------------
// Flash attention: q hi-only, S = q_hi*(K_hi + K_lo), P@V 1-product.
// 3-stage cp.async, one barrier/iter, 32-key tiles, 256 thr / 128 q-rows.
// grid = (L/128, H)
// ---------------------------------------------------------------------------
#define SK 72

__global__ __launch_bounds__(256, 2) void flash_f16p()
{
    __shared__ __align__(16) __half Ksh[3][32 * SK], Ksl[3][32 * SK], Vsh[3][32 * SK];

    const int h = blockIdx.y;
    const int tid = threadIdx.x;
    const int warp = tid >> 5, lane = tid & 31;
    const int gid = lane >> 2, tg = lane & 3;
    const int qrow0 = blockIdx.x * 128 + warp * 16;

    const int krow_ld = tid >> 3, kc8 = (tid & 7) * 8;
    const size_t kgoff = (size_t)krow_ld * N3D + D + h * DH + kc8;       // K'
    const size_t vgoff = kgoff + D;                                      // V
    const uint32_t ksoff = (uint32_t)((krow_ld * SK + kc8) * 2);

    // K ldsm (non-trans) lane offsets
    const int kr_lane = (lane & 7) + ((lane >> 4) & 1) * 8;
    const int kc_lane = ((lane >> 3) & 1) * 8;
    const uint32_t offK = (uint32_t)((kr_lane * SK + kc_lane) * 2);
    // V ldsm (trans) lane offsets
    const int vrow = ((lane >> 3) & 1) * 8 + (lane & 7);
    const int vcol = (lane >> 4) * 8;
    const uint32_t offV = (uint32_t)((vrow * SK + vcol) * 2);

    // Q hi fragments straight from gmem (scale folded into K')
    uint32_t qh[4][4];
    {
        const __half* qph = g_qkvh + (size_t)qrow0 * N3D + h * DH;
#pragma unroll
        for (int ks = 0; ks < 4; ks++) {
            const int c = ks * 16 + 2 * tg;
            qh[ks][0] = *(const uint32_t*)(qph + (size_t)gid * N3D + c);
            qh[ks][1] = *(const uint32_t*)(qph + (size_t)(gid + 8) * N3D + c);
            qh[ks][2] = *(const uint32_t*)(qph + (size_t)gid * N3D + c + 8);
            qh[ks][3] = *(const uint32_t*)(qph + (size_t)(gid + 8) * N3D + c + 8);
        }
    }

    float o[8][4];
#pragma unroll
    for (int nt = 0; nt < 8; nt++)
#pragma unroll
        for (int i = 0; i < 4; i++) o[nt][i] = 0.f;
    float m0 = -1e30f, m1 = -1e30f, l0 = 0.f, l1 = 0.f;

#pragma unroll
    for (int s = 0; s < 2; s++) {
        const size_t adv = (size_t)s * 32 * N3D;
        cp16(saddr(Ksh[s]) + ksoff, g_qkvh + kgoff + adv);
        cp16(saddr(Ksl[s]) + ksoff, g_qkvl + kgoff + adv);
        cp16(saddr(Vsh[s]) + ksoff, g_qkvh + vgoff + adv);
        cp_commit();
    }

    const int niter = L / 32;
    for (int it = 0; it < niter; it++) {
        const int b = it % 3;
        if (it == niter - 1) cp_wait<0>(); else cp_wait<1>();
        __syncthreads();
        if (it + 2 < niter) {
            const int s2 = (it + 2) % 3;
            const size_t adv = (size_t)(it + 2) * 32 * N3D;
            cp16(saddr(Ksh[s2]) + ksoff, g_qkvh + kgoff + adv);
            cp16(saddr(Ksl[s2]) + ksoff, g_qkvl + kgoff + adv);
            cp16(saddr(Vsh[s2]) + ksoff, g_qkvh + vgoff + adv);
            cp_commit();
        }

        // S = q_hi @ (K_hi + K_lo)^T   (16 x 32 per warp)
        float s[4][4];
#pragma unroll
        for (int nt = 0; nt < 4; nt++)
#pragma unroll
            for (int i = 0; i < 4; i++) s[nt][i] = 0.f;
        const uint32_t kh_base = saddr(Ksh[b]) + offK;
        const uint32_t kl_base = saddr(Ksl[b]) + offK;
#pragma unroll
        for (int ks = 0; ks < 4; ks++) {
#pragma unroll
            for (int ntp = 0; ntp < 2; ntp++) {
                uint32_t Kh[4], Kl[4];
                const uint32_t off = (uint32_t)((ntp * 16 * SK + ks * 16) * 2);
                ldsm_x4(Kh, kh_base + off);
                ldsm_x4(Kl, kl_base + off);
                mma_f16(s[2 * ntp],     qh[ks], Kh[0], Kh[1]);
                mma_f16(s[2 * ntp],     qh[ks], Kl[0], Kl[1]);
                mma_f16(s[2 * ntp + 1], qh[ks], Kh[2], Kh[3]);
                mma_f16(s[2 * ntp + 1], qh[ks], Kl[2], Kl[3]);
            }
        }

        // online softmax
        float tm0 = -1e30f, tm1 = -1e30f;
#pragma unroll
        for (int nt = 0; nt < 4; nt++) {
            tm0 = fmaxf(tm0, fmaxf(s[nt][0], s[nt][1]));
            tm1 = fmaxf(tm1, fmaxf(s[nt][2], s[nt][3]));
        }
        tm0 = fmaxf(tm0, __shfl_xor_sync(0xffffffffu, tm0, 1));
        tm0 = fmaxf(tm0, __shfl_xor_sync(0xffffffffu, tm0, 2));
        tm1 = fmaxf(tm1, __shfl_xor_sync(0xffffffffu, tm1, 1));
        tm1 = fmaxf(tm1, __shfl_xor_sync(0xffffffffu, tm1, 2));
        const float nm0 = fmaxf(m0, tm0), nm1 = fmaxf(m1, tm1);
        const float r0 = __expf(m0 - nm0), r1 = __expf(m1 - nm1);
        m0 = nm0; m1 = nm1;
        l0 *= r0; l1 *= r1;
#pragma unroll
        for (int nt = 0; nt < 8; nt++) {
            o[nt][0] *= r0; o[nt][1] *= r0;
            o[nt][2] *= r1; o[nt][3] *= r1;
        }
#pragma unroll
        for (int nt = 0; nt < 4; nt++) {
            s[nt][0] = __expf(s[nt][0] - m0);
            s[nt][1] = __expf(s[nt][1] - m0);
            s[nt][2] = __expf(s[nt][2] - m1);
            s[nt][3] = __expf(s[nt][3] - m1);
            l0 += s[nt][0] + s[nt][1];
            l1 += s[nt][2] + s[nt][3];
        }

        // P @ V (both 1-product)
        const uint32_t vh_base = saddr(Vsh[b]) + offV;
#pragma unroll
        for (int ks = 0; ks < 2; ks++) {
            uint32_t ah[4];
            ah[0] = cvt2(s[2 * ks][0],     s[2 * ks][1]);
            ah[1] = cvt2(s[2 * ks][2],     s[2 * ks][3]);
            ah[2] = cvt2(s[2 * ks + 1][0], s[2 * ks + 1][1]);
            ah[3] = cvt2(s[2 * ks + 1][2], s[2 * ks + 1][3]);
#pragma unroll
            for (int p = 0; p < 4; p++) {
                uint32_t Vf[4];
                ldsm_x4_t(Vf, vh_base + (uint32_t)((ks * 16 * SK + p * 16) * 2));
                mma_f16(o[2 * p],     ah, Vf[0], Vf[1]);
                mma_f16(o[2 * p + 1], ah, Vf[2], Vf[3]);
            }
        }
    }

    l0 += __shfl_xor_sync(0xffffffffu, l0, 1);
    l0 += __shfl_xor_sync(0xffffffffu, l0, 2);
    l1 += __shfl_xor_sync(0xffffffffu, l1, 1);
    l1 += __shfl_xor_sync(0xffffffffu, l1, 2);
    const float inv0 = 1.f / l0, inv1 = 1.f / l1;

    // write ctx hi only (out GEMM is A-hi-only)
    __half* oph = g_ctxh + (size_t)qrow0 * D + h * DH;
#pragma unroll
    for (int nt = 0; nt < 8; nt++) {
        const int col = nt * 8 + 2 * tg;
        *(uint32_t*)(oph + (size_t)gid * D + col) =
            cvt2(o[nt][0] * inv0, o[nt][1] * inv0);
        *(uint32_t*)(oph + (size_t)(gid + 8) * D + col) =
            cvt2(o[nt][2] * inv1, o[nt][3] * inv1);
    }
}

// ---------------------------------------------------------------------------
extern "C" void kernel_launch(void* const* d_in, const int* in_sizes, int n_in,
                              void* d_out, int out_size)
{
    const float* x    = (const float*)d_in[0];
    const float* Wqkv = (const float*)d_in[1];
    const float* bqkv = (const float*)d_in[2];
    const float* Wout = (const float*)d_in[3];
    const float* bout = (const float*)d_in[4];
    const float* rel  = (const float*)d_in[5];
    float* out = (float*)d_out;

    __half *xh, *wqh, *wql, *woh, *wol, *qkvh, *qkvl, *ctxh;
    { void* p; cudaGetSymbolAddress(&p, g_xh);   xh   = (__half*)p; }
    { void* p; cudaGetSymbolAddress(&p, g_wqh);  wqh  = (__half*)p; }
    { void* p; cudaGetSymbolAddress(&p, g_wql);  wql  = (__half*)p; }
    { void* p; cudaGetSymbolAddress(&p, g_woh);  woh  = (__half*)p; }
    { void* p; cudaGetSymbolAddress(&p, g_wol);  wol  = (__half*)p; }
    { void* p; cudaGetSymbolAddress(&p, g_qkvh); qkvh = (__half*)p; }
    { void* p; cudaGetSymbolAddress(&p, g_qkvl); qkvl = (__half*)p; }
    { void* p; cudaGetSymbolAddress(&p, g_ctxh); ctxh = (__half*)p; }

    cudaFuncSetAttribute(gemm_f16p, cudaFuncAttributeMaxDynamicSharedMemorySize,
                         GEMM_SMEM_BYTES);

    // 0) convert/split inputs
    cvt_kernel<<<(L * D / 4) / 256, 256>>>(x, xh, L * D / 4);
    split_kernel<<<(D * N3D / 4) / 256, 256>>>(Wqkv, wqh, wql, D * N3D / 4);
    split_kernel<<<(D * D / 4) / 256, 256>>>(Wout, woh, wol, D * D / 4);

    // 1) qkv = x_hi @ (Wqkv_hi + Wqkv_lo) + bqkv
    {
        dim3 grid(N3D / 128, L / 128);
        gemm_f16p<<<grid, 256, GEMM_SMEM_BYTES>>>(xh, wqh, wql, bqkv,
                                 nullptr, qkvh, qkvl, L, N3D, D, rel);
    }
    // 2) flash attention
    {
        dim3 grid(L / 128, H);
        flash_f16p<<<grid, 256>>>();
    }
    // 3) out = ctx_hi @ (Wout_hi + Wout_lo) + bout
    {
        dim3 grid(D / 128, L / 128);
        gemm_f16p<<<grid, 256, GEMM_SMEM_BYTES>>>(ctxh, woh, wol, bout,
                                 out, nullptr, nullptr, L, D, D, nullptr);
    }
}

// round 8
// speedup vs baseline: 8.6347x; 1.5325x over previous
#include <cuda_runtime.h>
#include <cuda_fp16.h>
#include <cstdint>

#define L    2048
#define D    1024
#define H    16
#define DH   64
#define N3D  3072
#define SCALE 0.125f

// Scratch (device globals — no allocation allowed)
__device__ __half g_xh[L * D];
__device__ __half g_wqh[D * N3D];     // Wqkv half, [K,N] row-major
__device__ __half g_woh[D * D];       // Wout half
__device__ __half g_qkvh[L * N3D];    // q | k'(rel+scale folded) | v
__device__ __half g_ctxh[L * D];

// ---------------------------------------------------------------------------
// helpers
// ---------------------------------------------------------------------------
__device__ __forceinline__ uint32_t cvt2(float x, float y) {
    __half2 h = __float22half2_rn(make_float2(x, y));
    return *(uint32_t*)&h;
}
__device__ __forceinline__ void mma_f16(float* d, const uint32_t* a, uint32_t b0, uint32_t b1) {
    asm volatile(
        "mma.sync.aligned.m16n8k16.row.col.f32.f16.f16.f32 "
        "{%0,%1,%2,%3},{%4,%5,%6,%7},{%8,%9},{%0,%1,%2,%3};\n"
        : "+f"(d[0]), "+f"(d[1]), "+f"(d[2]), "+f"(d[3])
        : "r"(a[0]), "r"(a[1]), "r"(a[2]), "r"(a[3]), "r"(b0), "r"(b1));
}
__device__ __forceinline__ void ldsm_x4(uint32_t* r, uint32_t addr) {
    asm volatile("ldmatrix.sync.aligned.m8n8.x4.shared.b16 {%0,%1,%2,%3},[%4];\n"
                 : "=r"(r[0]), "=r"(r[1]), "=r"(r[2]), "=r"(r[3]) : "r"(addr));
}
__device__ __forceinline__ void ldsm_x4_t(uint32_t* r, uint32_t addr) {
    asm volatile("ldmatrix.sync.aligned.m8n8.x4.trans.shared.b16 {%0,%1,%2,%3},[%4];\n"
                 : "=r"(r[0]), "=r"(r[1]), "=r"(r[2]), "=r"(r[3]) : "r"(addr));
}
__device__ __forceinline__ uint32_t saddr(const void* p) {
    return (uint32_t)__cvta_generic_to_shared(p);
}
__device__ __forceinline__ void cp16(uint32_t s, const void* g) {
    asm volatile("cp.async.cg.shared.global [%0],[%1],16;\n" :: "r"(s), "l"(g));
}
__device__ __forceinline__ void cp_commit() { asm volatile("cp.async.commit_group;\n"); }
template <int N> __device__ __forceinline__ void cp_wait() {
    asm volatile("cp.async.wait_group %0;\n" :: "n"(N));
}

// ---------------------------------------------------------------------------
// fp32 -> fp16 convert
// ---------------------------------------------------------------------------
__global__ __launch_bounds__(256) void cvt_kernel(
    const float* __restrict__ src, __half* __restrict__ hi, int n4)
{
    int i = blockIdx.x * 256 + threadIdx.x;
    if (i < n4) {
        float4 f = ((const float4*)src)[i];
        ((uint2*)hi)[i] = make_uint2(cvt2(f.x, f.y), cvt2(f.z, f.w));
    }
}

// ---------------------------------------------------------------------------
// fp16 GEMM (single product): C = A[M,K] @ B[K,N] + bias.
// 3-stage cp.async, one barrier/iter, BK=32, tile 128x128, 256 thr,
// warps 4(m)x2(n). Ch!=null: half output, K' cols [1024,2048) get
// rel fold + 0.125 scale. Else fp32 to Cf.
// ---------------------------------------------------------------------------
#define SA 40          // A row stride (32 + 8 pad)
#define SB 136         // B row stride (128 + 8 pad)
#define ASTG (128 * SA)
#define BSTG (32 * SB)
#define GEMM_SMEM_BYTES (3 * (ASTG + BSTG) * 2)

__global__ __launch_bounds__(256, 2) void gemm_f16s(
    const __half* __restrict__ Ah, const __half* __restrict__ Bh,
    const float* __restrict__ bias,
    float* __restrict__ Cf, __half* __restrict__ Ch,
    int M, int N, int K, const float* __restrict__ rel)
{
    extern __shared__ __align__(16) __half dsm[];
    __half* As = dsm;                 // [3][ASTG]
    __half* Bs = dsm + 3 * ASTG;      // [3][BSTG]

    const int tid = threadIdx.x;
    const int warp = tid >> 5, lane = tid & 31;
    const int gid = lane >> 2, tg = lane & 3;
    const int bm = blockIdx.y * 128, bn = blockIdx.x * 128;
    const int wm = (warp >> 1) * 32, wn = (warp & 1) * 64;

    float acc[2][8][4];
#pragma unroll
    for (int mt = 0; mt < 2; mt++)
#pragma unroll
        for (int nt = 0; nt < 8; nt++)
#pragma unroll
            for (int i = 0; i < 4; i++) acc[mt][nt][i] = 0.f;

    // cp.async: A 128 rows x 4 chunks (512), B 32 rows x 16 chunks (512):
    // 2 chunks per thread each
    int arow[2], acol[2], brow[2], bcol[2];
#pragma unroll
    for (int i = 0; i < 2; i++) {
        const int ia = tid + i * 256;
        arow[i] = ia >> 2;  acol[i] = (ia & 3) * 8;
        brow[i] = ia >> 4;  bcol[i] = (ia & 15) * 8;
    }
    size_t agoff[2], bgoff[2];
    uint32_t asoff[2], bsoff[2];
#pragma unroll
    for (int i = 0; i < 2; i++) {
        agoff[i] = (size_t)(bm + arow[i]) * K + acol[i];
        bgoff[i] = (size_t)brow[i] * N + bn + bcol[i];
        asoff[i] = (uint32_t)((arow[i] * SA + acol[i]) * 2);
        bsoff[i] = (uint32_t)((brow[i] * SB + bcol[i]) * 2);
    }

    // ldmatrix lane offsets
    const int l15 = lane & 15, lhi = lane >> 4;
    const int krow = ((lane >> 3) & 1) * 8 + (lane & 7);
    const uint32_t offA = (uint32_t)(((wm + l15) * SA + lhi * 8) * 2);
    const uint32_t offB = (uint32_t)((krow * SB + wn + lhi * 8) * 2);

    const int nkt = K >> 5;   // BK = 32

    // prologue: stages 0,1
#pragma unroll
    for (int s = 0; s < 2; s++) {
#pragma unroll
        for (int i = 0; i < 2; i++) {
            cp16(saddr(As + s * ASTG) + asoff[i], Ah + agoff[i] + s * 32);
            cp16(saddr(Bs + s * BSTG) + bsoff[i], Bh + bgoff[i] + (size_t)s * 32 * N);
        }
        cp_commit();
    }

    for (int kt = 0; kt < nkt; kt++) {
        const int b = kt % 3;
        if (kt == nkt - 1) cp_wait<0>(); else cp_wait<1>();
        __syncthreads();
        if (kt + 2 < nkt) {
            const int s2 = (kt + 2) % 3;
#pragma unroll
            for (int i = 0; i < 2; i++) {
                cp16(saddr(As + s2 * ASTG) + asoff[i],
                     Ah + agoff[i] + (size_t)(kt + 2) * 32);
                cp16(saddr(Bs + s2 * BSTG) + bsoff[i],
                     Bh + bgoff[i] + (size_t)(kt + 2) * 32 * N);
            }
            cp_commit();
        }

        const uint32_t a_base = saddr(As + b * ASTG) + offA;
        const uint32_t b_base = saddr(Bs + b * BSTG) + offB;
#pragma unroll
        for (int ks = 0; ks < 2; ks++) {           // two K=16 sub-steps
            uint32_t Af[2][4];
#pragma unroll
            for (int mt = 0; mt < 2; mt++)
                ldsm_x4(Af[mt], a_base + (uint32_t)((mt * 16 * SA + ks * 16) * 2));
#pragma unroll
            for (int p = 0; p < 4; p++) {
                uint32_t Bf[4];
                ldsm_x4_t(Bf, b_base + (uint32_t)((ks * 16 * SB) * 2) + p * 32);
#pragma unroll
                for (int mt = 0; mt < 2; mt++) {
                    mma_f16(acc[mt][2 * p],     Af[mt], Bf[0], Bf[1]);
                    mma_f16(acc[mt][2 * p + 1], Af[mt], Bf[2], Bf[3]);
                }
            }
        }
    }

    // epilogue
#pragma unroll
    for (int mt = 0; mt < 2; mt++) {
#pragma unroll
        for (int nt = 0; nt < 8; nt++) {
            const int col = bn + wn + nt * 8 + 2 * tg;
            const float bi0 = bias[col], bi1 = bias[col + 1];
            const bool kcol = (col >= 1024) && (col < 2048);
#pragma unroll
            for (int hf = 0; hf < 2; hf++) {
                const int row = bm + wm + mt * 16 + gid + hf * 8;
                float v0 = acc[mt][nt][hf * 2 + 0] + bi0;
                float v1 = acc[mt][nt][hf * 2 + 1] + bi1;
                if (Ch != nullptr) {
                    if (kcol) {                    // K' section
                        if (row >= 1) {
                            v0 += rel[(size_t)(row - 1) * 64 + (col & 63)];
                            v1 += rel[(size_t)(row - 1) * 64 + ((col + 1) & 63)];
                        }
                        v0 *= SCALE; v1 *= SCALE;  // exact pow2
                    }
                    *(uint32_t*)(Ch + (size_t)row * N + col) = cvt2(v0, v1);
                } else {
                    *(float2*)(Cf + (size_t)row * N + col) = make_float2(v0, v1);
                }
            }
        }
    }
}

// ---------------------------------------------------------------------------
// Flash attention: all single-product fp16. 3-stage cp.async, 32-key tiles,
// 256 thr / 128 q-rows per block. grid = (L/128, H)
// ---------------------------------------------------------------------------
#define SK 72

__global__ __launch_bounds__(256, 2) void flash_f16s()
{
    __shared__ __align__(16) __half Ksh[3][32 * SK], Vsh[3][32 * SK];

    const int h = blockIdx.y;
    const int tid = threadIdx.x;
    const int warp = tid >> 5, lane = tid & 31;
    const int gid = lane >> 2, tg = lane & 3;
    const int qrow0 = blockIdx.x * 128 + warp * 16;

    const int krow_ld = tid >> 3, kc8 = (tid & 7) * 8;
    const size_t kgoff = (size_t)krow_ld * N3D + D + h * DH + kc8;   // K'
    const size_t vgoff = kgoff + D;                                  // V
    const uint32_t ksoff = (uint32_t)((krow_ld * SK + kc8) * 2);

    // K ldsm (non-trans) lane offsets
    const int kr_lane = (lane & 7) + ((lane >> 4) & 1) * 8;
    const int kc_lane = ((lane >> 3) & 1) * 8;
    const uint32_t offK = (uint32_t)((kr_lane * SK + kc_lane) * 2);
    // V ldsm (trans) lane offsets
    const int vrow = ((lane >> 3) & 1) * 8 + (lane & 7);
    const int vcol = (lane >> 4) * 8;
    const uint32_t offV = (uint32_t)((vrow * SK + vcol) * 2);

    // Q fragments straight from gmem (scale folded into K')
    uint32_t qh[4][4];
    {
        const __half* qph = g_qkvh + (size_t)qrow0 * N3D + h * DH;
#pragma unroll
        for (int ks = 0; ks < 4; ks++) {
            const int c = ks * 16 + 2 * tg;
            qh[ks][0] = *(const uint32_t*)(qph + (size_t)gid * N3D + c);
            qh[ks][1] = *(const uint32_t*)(qph + (size_t)(gid + 8) * N3D + c);
            qh[ks][2] = *(const uint32_t*)(qph + (size_t)gid * N3D + c + 8);
            qh[ks][3] = *(const uint32_t*)(qph + (size_t)(gid + 8) * N3D + c + 8);
        }
    }

    float o[8][4];
#pragma unroll
    for (int nt = 0; nt < 8; nt++)
#pragma unroll
        for (int i = 0; i < 4; i++) o[nt][i] = 0.f;
    float m0 = -1e30f, m1 = -1e30f, l0 = 0.f, l1 = 0.f;

#pragma unroll
    for (int s = 0; s < 2; s++) {
        const size_t adv = (size_t)s * 32 * N3D;
        cp16(saddr(Ksh[s]) + ksoff, g_qkvh + kgoff + adv);
        cp16(saddr(Vsh[s]) + ksoff, g_qkvh + vgoff + adv);
        cp_commit();
    }

    const int niter = L / 32;
    for (int it = 0; it < niter; it++) {
        const int b = it % 3;
        if (it == niter - 1) cp_wait<0>(); else cp_wait<1>();
        __syncthreads();
        if (it + 2 < niter) {
            const int s2 = (it + 2) % 3;
            const size_t adv = (size_t)(it + 2) * 32 * N3D;
            cp16(saddr(Ksh[s2]) + ksoff, g_qkvh + kgoff + adv);
            cp16(saddr(Vsh[s2]) + ksoff, g_qkvh + vgoff + adv);
            cp_commit();
        }

        // S = q @ K'^T (16 x 32 per warp, single product)
        float s[4][4];
#pragma unroll
        for (int nt = 0; nt < 4; nt++)
#pragma unroll
            for (int i = 0; i < 4; i++) s[nt][i] = 0.f;
        const uint32_t kh_base = saddr(Ksh[b]) + offK;
#pragma unroll
        for (int ks = 0; ks < 4; ks++) {
#pragma unroll
            for (int ntp = 0; ntp < 2; ntp++) {
                uint32_t Kh[4];
                ldsm_x4(Kh, kh_base + (uint32_t)((ntp * 16 * SK + ks * 16) * 2));
                mma_f16(s[2 * ntp],     qh[ks], Kh[0], Kh[1]);
                mma_f16(s[2 * ntp + 1], qh[ks], Kh[2], Kh[3]);
            }
        }

        // online softmax
        float tm0 = -1e30f, tm1 = -1e30f;
#pragma unroll
        for (int nt = 0; nt < 4; nt++) {
            tm0 = fmaxf(tm0, fmaxf(s[nt][0], s[nt][1]));
            tm1 = fmaxf(tm1, fmaxf(s[nt][2], s[nt][3]));
        }
        tm0 = fmaxf(tm0, __shfl_xor_sync(0xffffffffu, tm0, 1));
        tm0 = fmaxf(tm0, __shfl_xor_sync(0xffffffffu, tm0, 2));
        tm1 = fmaxf(tm1, __shfl_xor_sync(0xffffffffu, tm1, 1));
        tm1 = fmaxf(tm1, __shfl_xor_sync(0xffffffffu, tm1, 2));
        const float nm0 = fmaxf(m0, tm0), nm1 = fmaxf(m1, tm1);
        const float r0 = __expf(m0 - nm0), r1 = __expf(m1 - nm1);
        m0 = nm0; m1 = nm1;
        l0 *= r0; l1 *= r1;
#pragma unroll
        for (int nt = 0; nt < 8; nt++) {
            o[nt][0] *= r0; o[nt][1] *= r0;
            o[nt][2] *= r1; o[nt][3] *= r1;
        }
#pragma unroll
        for (int nt = 0; nt < 4; nt++) {
            s[nt][0] = __expf(s[nt][0] - m0);
            s[nt][1] = __expf(s[nt][1] - m0);
            s[nt][2] = __expf(s[nt][2] - m1);
            s[nt][3] = __expf(s[nt][3] - m1);
            l0 += s[nt][0] + s[nt][1];
            l1 += s[nt][2] + s[nt][3];
        }

        // P @ V (single product)
        const uint32_t vh_base = saddr(Vsh[b]) + offV;
#pragma unroll
        for (int ks = 0; ks < 2; ks++) {
            uint32_t ah[4];
            ah[0] = cvt2(s[2 * ks][0],     s[2 * ks][1]);
            ah[1] = cvt2(s[2 * ks][2],     s[2 * ks][3]);
            ah[2] = cvt2(s[2 * ks + 1][0], s[2 * ks + 1][1]);
            ah[3] = cvt2(s[2 * ks + 1][2], s[2 * ks + 1][3]);
#pragma unroll
            for (int p = 0; p < 4; p++) {
                uint32_t Vf[4];
                ldsm_x4_t(Vf, vh_base + (uint32_t)((ks * 16 * SK + p * 16) * 2));
                mma_f16(o[2 * p],     ah, Vf[0], Vf[1]);
                mma_f16(o[2 * p + 1], ah, Vf[2], Vf[3]);
            }
        }
    }

    l0 += __shfl_xor_sync(0xffffffffu, l0, 1);
    l0 += __shfl_xor_sync(0xffffffffu, l0, 2);
    l1 += __shfl_xor_sync(0xffffffffu, l1, 1);
    l1 += __shfl_xor_sync(0xffffffffu, l1, 2);
    const float inv0 = 1.f / l0, inv1 = 1.f / l1;

    __half* oph = g_ctxh + (size_t)qrow0 * D + h * DH;
#pragma unroll
    for (int nt = 0; nt < 8; nt++) {
        const int col = nt * 8 + 2 * tg;
        *(uint32_t*)(oph + (size_t)gid * D + col) =
            cvt2(o[nt][0] * inv0, o[nt][1] * inv0);
        *(uint32_t*)(oph + (size_t)(gid + 8) * D + col) =
            cvt2(o[nt][2] * inv1, o[nt][3] * inv1);
    }
}

// ---------------------------------------------------------------------------
extern "C" void kernel_launch(void* const* d_in, const int* in_sizes, int n_in,
                              void* d_out, int out_size)
{
    const float* x    = (const float*)d_in[0];
    const float* Wqkv = (const float*)d_in[1];
    const float* bqkv = (const float*)d_in[2];
    const float* Wout = (const float*)d_in[3];
    const float* bout = (const float*)d_in[4];
    const float* rel  = (const float*)d_in[5];
    float* out = (float*)d_out;

    __half *xh, *wqh, *woh, *qkvh, *ctxh;
    { void* p; cudaGetSymbolAddress(&p, g_xh);   xh   = (__half*)p; }
    { void* p; cudaGetSymbolAddress(&p, g_wqh);  wqh  = (__half*)p; }
    { void* p; cudaGetSymbolAddress(&p, g_woh);  woh  = (__half*)p; }
    { void* p; cudaGetSymbolAddress(&p, g_qkvh); qkvh = (__half*)p; }
    { void* p; cudaGetSymbolAddress(&p, g_ctxh); ctxh = (__half*)p; }

    cudaFuncSetAttribute(gemm_f16s, cudaFuncAttributeMaxDynamicSharedMemorySize,
                         GEMM_SMEM_BYTES);

    // 0) convert inputs to fp16
    cvt_kernel<<<(L * D / 4) / 256, 256>>>(x, xh, L * D / 4);
    cvt_kernel<<<(D * N3D / 4) / 256, 256>>>(Wqkv, wqh, D * N3D / 4);
    cvt_kernel<<<(D * D / 4) / 256, 256>>>(Wout, woh, D * D / 4);

    // 1) qkv = x @ Wqkv + bqkv (half out; rel fold + scale on K' section)
    {
        dim3 grid(N3D / 128, L / 128);
        gemm_f16s<<<grid, 256, GEMM_SMEM_BYTES>>>(xh, wqh, bqkv,
                                                  nullptr, qkvh, L, N3D, D, rel);
    }
    // 2) flash attention
    {
        dim3 grid(L / 128, H);
        flash_f16s<<<grid, 256>>>();
    }
    // 3) out = ctx @ Wout + bout (fp32 out)
    {
        dim3 grid(D / 128, L / 128);
        gemm_f16s<<<grid, 256, GEMM_SMEM_BYTES>>>(ctxh, woh, bout,
                                                  out, nullptr, L, D, D, nullptr);
    }
}